// round 10
// baseline (speedup 1.0000x reference)
#include <cuda_runtime.h>
#include <cuda_bf16.h>
#include <cstdint>
#include <cstddef>

// Problem constants
#define DIMC   768
#define NHEADS 12
#define HDIM   64
#define BATCH  8
#define LQ     1024
#define LKV    1024
#define SCALE  0.125f
#define KVSTR  (2 * DIMC)       // 1536 (elements)

#define MROWS  (BATCH * LQ)     // 8192

// bf16 split scratch
__device__ __nv_bfloat16 g_qh  [(size_t)MROWS * DIMC];
__device__ __nv_bfloat16 g_ql  [(size_t)MROWS * DIMC];
__device__ __nv_bfloat16 g_kvh [(size_t)MROWS * DIMC];
__device__ __nv_bfloat16 g_kvl [(size_t)MROWS * DIMC];
__device__ __nv_bfloat16 g_wqh [(size_t)DIMC * DIMC];
__device__ __nv_bfloat16 g_wql [(size_t)DIMC * DIMC];
__device__ __nv_bfloat16 g_wkh [(size_t)2 * DIMC * DIMC];
__device__ __nv_bfloat16 g_wkl [(size_t)2 * DIMC * DIMC];
__device__ __nv_bfloat16 g_wph [(size_t)DIMC * DIMC];
__device__ __nv_bfloat16 g_wpl [(size_t)DIMC * DIMC];
__device__ __nv_bfloat16 g_PQh [(size_t)MROWS * DIMC];
__device__ __nv_bfloat16 g_PQl [(size_t)MROWS * DIMC];
__device__ __nv_bfloat16 g_PKh [(size_t)MROWS * 2 * DIMC];
__device__ __nv_bfloat16 g_PKl [(size_t)MROWS * 2 * DIMC];
__device__ __nv_bfloat16 g_oh  [(size_t)MROWS * DIMC];
__device__ __nv_bfloat16 g_ol  [(size_t)MROWS * DIMC];

// ---------------------------------------------------------------------------
__device__ __forceinline__ uint32_t smem_u32(const void* p) {
    uint32_t a;
    asm("{ .reg .u64 t; cvta.to.shared.u64 t, %1; cvt.u32.u64 %0, t; }" : "=r"(a) : "l"(p));
    return a;
}
__device__ __forceinline__ void ldsm4(uint32_t* r, uint32_t addr) {
    asm volatile("ldmatrix.sync.aligned.m8n8.x4.shared.b16 {%0,%1,%2,%3}, [%4];"
        : "=r"(r[0]), "=r"(r[1]), "=r"(r[2]), "=r"(r[3]) : "r"(addr));
}
__device__ __forceinline__ void ldsm4t(uint32_t* r, uint32_t addr) {
    asm volatile("ldmatrix.sync.aligned.m8n8.x4.trans.shared.b16 {%0,%1,%2,%3}, [%4];"
        : "=r"(r[0]), "=r"(r[1]), "=r"(r[2]), "=r"(r[3]) : "r"(addr));
}
__device__ __forceinline__ void mma16816(float* d, const uint32_t* a, const uint32_t* b) {
    asm volatile("mma.sync.aligned.m16n8k16.row.col.f32.bf16.bf16.f32 "
        "{%0,%1,%2,%3}, {%4,%5,%6,%7}, {%8,%9}, {%0,%1,%2,%3};"
        : "+f"(d[0]), "+f"(d[1]), "+f"(d[2]), "+f"(d[3])
        : "r"(a[0]), "r"(a[1]), "r"(a[2]), "r"(a[3]), "r"(b[0]), "r"(b[1]));
}
__device__ __forceinline__ void cp16(uint32_t dst, const void* src) {
    asm volatile("cp.async.cg.shared.global [%0], [%1], 16;" :: "r"(dst), "l"(src) : "memory");
}
#define CP_COMMIT() asm volatile("cp.async.commit_group;" ::: "memory")

__device__ __forceinline__ uint32_t packbf(float a, float b) {
    __nv_bfloat162 t = __floats2bfloat162_rn(a, b);
    return *(uint32_t*)&t;
}

// swizzled byte offset, 128B rows (8 x 16B units)
__device__ __forceinline__ uint32_t swz(int row, int c16) {
    return (uint32_t)(row * 128 + ((c16 ^ (row & 7)) << 4));
}
// swizzled byte offset, 64B rows (4 x 16B units)
__device__ __forceinline__ uint32_t swz64(int row, int c16) {
    return (uint32_t)(row * 64 + ((c16 ^ ((row >> 1) & 3)) << 4));
}

// ---------------------------------------------------------------------------
// GEMM: tile 128(M)x64(N), 256 threads, warp 32x32 (4x2 grid),
// K-chunk 32, 4-stage cp.async pipeline, 2 CTAs/SM.
// ---------------------------------------------------------------------------
#define GSTG   24576          // AH 8K | AL 8K | WH 4K | WL 4K
#define GB_AH  0
#define GB_AL  8192
#define GB_WH  16384
#define GB_WL  20480
#define GEMM_SMEM (4 * GSTG)  // 98304

// stage A chunk: 128 rows x 32 bf16 = 512 16B lines (2/thread)
__device__ __forceinline__ void stageA32(uint32_t sdst, const __nv_bfloat16* rowbase,
                                         int K, int k0, int tid) {
#pragma unroll
    for (int rep = 0; rep < 2; rep++) {
        int i = tid + rep * 256;
        int row = i >> 2, c16 = i & 3;
        cp16(sdst + swz64(row, c16), rowbase + (size_t)row * K + k0 + c16 * 8);
    }
}
// stage W chunk: 64 rows x 32 bf16 = 256 16B lines (1/thread)
__device__ __forceinline__ void stageW32(uint32_t sdst, const __nv_bfloat16* rowbase,
                                         int K, int k0, int tid) {
    int row = tid >> 2, c16 = tid & 3;
    cp16(sdst + swz64(row, c16), rowbase + (size_t)row * K + k0 + c16 * 8);
}

__device__ __forceinline__
void gemm_body(const __nv_bfloat16* __restrict__ Ah, const __nv_bfloat16* __restrict__ Al,
               const __nv_bfloat16* __restrict__ Wh, const __nv_bfloat16* __restrict__ Wl,
               const float* __restrict__ bias, float* __restrict__ C,
               __nv_bfloat16* __restrict__ Ch, __nv_bfloat16* __restrict__ Cl,
               int N, int K, int m0, int n0, char* sm)
{
    const uint32_t smb = smem_u32(sm);
    const int tid = threadIdx.x;
    const int wid = tid >> 5, lane = tid & 31;
    const int wm = wid >> 1, wn = wid & 1;          // 4x2 warp grid, warp = 32x32

    const __nv_bfloat16* Ahb = Ah + (size_t)m0 * K;
    const __nv_bfloat16* Alb = Al + (size_t)m0 * K;
    const __nv_bfloat16* Whb = Wh + (size_t)n0 * K;
    const __nv_bfloat16* Wlb = Wl + (size_t)n0 * K;

    const int g = lane >> 3, r = lane & 7;
    const int arl = (g & 1) * 8 + r;
    const int acs = g >> 1;
    const int brl = (g >> 1) * 8 + r;
    const int bcs = g & 1;

    float acc[2][4][4];
#pragma unroll
    for (int i = 0; i < 2; i++)
#pragma unroll
        for (int j = 0; j < 4; j++)
#pragma unroll
            for (int k = 0; k < 4; k++) acc[i][j][k] = 0.f;

    const int NC = K >> 5;   // 24 chunks of 32

    // prologue: stage chunks 0..2
#pragma unroll
    for (int c = 0; c < 3; ++c) {
        uint32_t sb = smb + c * GSTG;
        stageA32(sb + GB_AH, Ahb, K, c << 5, tid);
        stageA32(sb + GB_AL, Alb, K, c << 5, tid);
        stageW32(sb + GB_WH, Whb, K, c << 5, tid);
        stageW32(sb + GB_WL, Wlb, K, c << 5, tid);
        CP_COMMIT();
    }

    for (int c = 0; c < NC; ++c) {
        asm volatile("cp.async.wait_group 2;" ::: "memory");
        __syncthreads();

        // prefetch chunk c+3 (overwrites chunk c-1's buffer; safe after barrier)
        if (c + 3 < NC) {
            uint32_t sb = smb + ((c + 3) & 3) * GSTG;
            int k0 = (c + 3) << 5;
            stageA32(sb + GB_AH, Ahb, K, k0, tid);
            stageA32(sb + GB_AL, Alb, K, k0, tid);
            stageW32(sb + GB_WH, Whb, K, k0, tid);
            stageW32(sb + GB_WL, Wlb, K, k0, tid);
        }
        CP_COMMIT();   // empty group in tail keeps wait_group arithmetic uniform

        const uint32_t sb = smb + (c & 3) * GSTG;
        const uint32_t bAh = sb + GB_AH, bAl = sb + GB_AL;
        const uint32_t bWh = sb + GB_WH, bWl = sb + GB_WL;

#pragma unroll
        for (int s = 0; s < 2; ++s) {
            uint32_t ah[2][4], al[2][4], bh[2][4], bl[2][4];
#pragma unroll
            for (int mt = 0; mt < 2; ++mt) {
                ldsm4(ah[mt], bAh + swz64(wm * 32 + mt * 16 + arl, s * 2 + acs));
                ldsm4(al[mt], bAl + swz64(wm * 32 + mt * 16 + arl, s * 2 + acs));
            }
#pragma unroll
            for (int p = 0; p < 2; ++p) {
                ldsm4(bh[p], bWh + swz64(wn * 32 + p * 16 + brl, s * 2 + bcs));
                ldsm4(bl[p], bWl + swz64(wn * 32 + p * 16 + brl, s * 2 + bcs));
            }
#pragma unroll
            for (int mt = 0; mt < 2; ++mt)
#pragma unroll
                for (int nt = 0; nt < 4; ++nt)
                    mma16816(acc[mt][nt], ah[mt], &bh[nt >> 1][(nt & 1) * 2]);
#pragma unroll
            for (int mt = 0; mt < 2; ++mt)
#pragma unroll
                for (int nt = 0; nt < 4; ++nt)
                    mma16816(acc[mt][nt], ah[mt], &bl[nt >> 1][(nt & 1) * 2]);
#pragma unroll
            for (int mt = 0; mt < 2; ++mt)
#pragma unroll
                for (int nt = 0; nt < 4; ++nt)
                    mma16816(acc[mt][nt], al[mt], &bh[nt >> 1][(nt & 1) * 2]);
        }
    }

    const int er = lane >> 2, ec = (lane & 3) * 2;
    if (Ch) {
#pragma unroll
        for (int mt = 0; mt < 2; ++mt) {
#pragma unroll
            for (int nt = 0; nt < 4; ++nt) {
                int grow = m0 + wm * 32 + mt * 16 + er;
                int gcol = n0 + wn * 32 + nt * 8 + ec;
#pragma unroll
                for (int rr = 0; rr < 2; ++rr) {
                    float v0 = acc[mt][nt][rr * 2 + 0];
                    float v1 = acc[mt][nt][rr * 2 + 1];
                    __nv_bfloat16 h0 = __float2bfloat16_rn(v0);
                    __nv_bfloat16 h1 = __float2bfloat16_rn(v1);
                    float l0f = v0 - __bfloat162float(h0);
                    float l1f = v1 - __bfloat162float(h1);
                    size_t off = (size_t)(grow + rr * 8) * N + gcol;
                    *(uint32_t*)(Ch + off) = packbf(__bfloat162float(h0), __bfloat162float(h1));
                    *(uint32_t*)(Cl + off) = packbf(l0f, l1f);
                }
            }
        }
    } else {
#pragma unroll
        for (int mt = 0; mt < 2; ++mt) {
#pragma unroll
            for (int nt = 0; nt < 4; ++nt) {
                int grow = m0 + wm * 32 + mt * 16 + er;
                int gcol = n0 + wn * 32 + nt * 8 + ec;
                float b0 = 0.f, b1 = 0.f;
                if (bias) { b0 = bias[gcol]; b1 = bias[gcol + 1]; }
                float2 v0 = make_float2(acc[mt][nt][0] + b0, acc[mt][nt][1] + b1);
                float2 v1 = make_float2(acc[mt][nt][2] + b0, acc[mt][nt][3] + b1);
                *(float2*)(C + (size_t)grow * N + gcol) = v0;
                *(float2*)(C + (size_t)(grow + 8) * N + gcol) = v1;
            }
        }
    }
}

// Combined Q + KV projection gemm.
__global__ __launch_bounds__(256, 2)
void gemm_qkv(const __nv_bfloat16* __restrict__ qh, const __nv_bfloat16* __restrict__ ql,
              const __nv_bfloat16* __restrict__ wqh, const __nv_bfloat16* __restrict__ wql,
              __nv_bfloat16* __restrict__ PQh, __nv_bfloat16* __restrict__ PQl,
              const __nv_bfloat16* __restrict__ kvh, const __nv_bfloat16* __restrict__ kvl,
              const __nv_bfloat16* __restrict__ wkh, const __nv_bfloat16* __restrict__ wkl,
              __nv_bfloat16* __restrict__ PKh, __nv_bfloat16* __restrict__ PKl)
{
    extern __shared__ char sm[];
    int bx = blockIdx.x;
    if (bx < 768) {
        int nb = bx % 12, mb = bx / 12;
        gemm_body(qh, ql, wqh, wql, nullptr, nullptr, PQh, PQl,
                  DIMC, DIMC, mb * 128, nb * 64, sm);
    } else {
        int t = bx - 768;
        int nb = t % 24, mb = t / 24;
        gemm_body(kvh, kvl, wkh, wkl, nullptr, nullptr, PKh, PKl,
                  2 * DIMC, DIMC, mb * 128, nb * 64, sm);
    }
}

// Output projection gemm (fp32 out + bias).
__global__ __launch_bounds__(256, 2)
void gemm_proj(const __nv_bfloat16* __restrict__ oh, const __nv_bfloat16* __restrict__ ol,
               const __nv_bfloat16* __restrict__ wph, const __nv_bfloat16* __restrict__ wpl,
               const float* __restrict__ bias, float* __restrict__ out)
{
    extern __shared__ char sm[];
    int nb = blockIdx.x % 12, mb = blockIdx.x / 12;
    gemm_body(oh, ol, wph, wpl, bias, out, nullptr, nullptr,
              DIMC, DIMC, mb * 128, nb * 64, sm);
}

// ---------------------------------------------------------------------------
// One merged fp32 -> (hi,lo) bf16 split over all 5 input arrays.
// ---------------------------------------------------------------------------
#define N4_Q   ((size_t)MROWS * DIMC / 4)
#define N4_W1  ((size_t)DIMC * DIMC / 4)
#define N4_W2  ((size_t)2 * DIMC * DIMC / 4)
#define N4_TOT (N4_Q + N4_Q + N4_W1 + N4_W2 + N4_W1)

__global__ __launch_bounds__(256)
void cvt_all(const float4* __restrict__ q,   uint2* __restrict__ qh,  uint2* __restrict__ ql,
             const float4* __restrict__ kv,  uint2* __restrict__ kvh, uint2* __restrict__ kvl,
             const float4* __restrict__ wq,  uint2* __restrict__ wqh, uint2* __restrict__ wql,
             const float4* __restrict__ wkv, uint2* __restrict__ wkh, uint2* __restrict__ wkl,
             const float4* __restrict__ wp,  uint2* __restrict__ wph, uint2* __restrict__ wpl)
{
    size_t i = (size_t)blockIdx.x * blockDim.x + threadIdx.x;
    if (i >= N4_TOT) return;
    const float4* src; uint2 *hi, *lo; size_t j = i;
    if (j < N4_Q)                 { src = q;   hi = qh;  lo = ql;  }
    else if ((j -= N4_Q) < N4_Q)  { src = kv;  hi = kvh; lo = kvl; }
    else if ((j -= N4_Q) < N4_W1) { src = wq;  hi = wqh; lo = wql; }
    else if ((j -= N4_W1) < N4_W2){ src = wkv; hi = wkh; lo = wkl; }
    else { j -= N4_W2;              src = wp;  hi = wph; lo = wpl; }

    float4 x = src[j];
    __nv_bfloat162 h01 = __floats2bfloat162_rn(x.x, x.y);
    __nv_bfloat162 h23 = __floats2bfloat162_rn(x.z, x.w);
    float r0 = x.x - __low2float(h01), r1 = x.y - __high2float(h01);
    float r2 = x.z - __low2float(h23), r3 = x.w - __high2float(h23);
    __nv_bfloat162 l01 = __floats2bfloat162_rn(r0, r1);
    __nv_bfloat162 l23 = __floats2bfloat162_rn(r2, r3);
    hi[j] = make_uint2(*(uint32_t*)&h01, *(uint32_t*)&h23);
    lo[j] = make_uint2(*(uint32_t*)&l01, *(uint32_t*)&l23);
}

// ---------------------------------------------------------------------------
// Tensor-core flash attention, bf16-split. kv-tile 32, 2 CTAs/SM.
// smem: Qh|Ql (32KB) + 2 stages { KH,KL,VH,VL 4KB each | pos 18KB } = 100KB
// ---------------------------------------------------------------------------
#define AQ_H     0
#define AQ_L     16384
#define AST_BASE 32768
#define AST_KH   0
#define AST_KL   4096
#define AST_VH   8192
#define AST_VL   12288
#define AST_P    16384
#define AST_SIZE 34816                    // 16384 + 18432
#define ATTN_SMEM (AST_BASE + 2 * AST_SIZE)   // 102400

__global__ __launch_bounds__(256, 2)
void attn_mma(const __nv_bfloat16* __restrict__ Qh, const __nv_bfloat16* __restrict__ Ql,
              const __nv_bfloat16* __restrict__ KVh, const __nv_bfloat16* __restrict__ KVl,
              const float* __restrict__ pos,
              __nv_bfloat16* __restrict__ Oh, __nv_bfloat16* __restrict__ Ol)
{
    extern __shared__ char sm[];
    const uint32_t smb = smem_u32(sm);
    const int tid = threadIdx.x, wid = tid >> 5, lane = tid & 31;
    const int b = blockIdx.z, h = blockIdx.y;
    const int q0 = blockIdx.x * 128;

    const int g = lane >> 3, r = lane & 7;
    const int arl = (g & 1) * 8 + r, acs = g >> 1;
    const int brl = (g >> 1) * 8 + r, bcs = g & 1;
    const int er = lane >> 2, ec = (lane & 3) * 2;

    // stage Q tile (hi/lo) once: 128 rows x 64 bf16 each
    const size_t qrow0 = (size_t)(b * LQ + q0);
    for (int i = tid; i < 128 * 8; i += 256) {
        int row = i >> 3, c16 = i & 7;
        size_t off = (qrow0 + row) * DIMC + h * HDIM + c16 * 8;
        uint32_t d = swz(row, c16);
        cp16(smb + AQ_H + d, Qh + off);
        cp16(smb + AQ_L + d, Ql + off);
    }
    CP_COMMIT();

    const float* posbase = pos + ((size_t)(h * LQ + q0)) * LKV;

    // stage kv tile c (32 rows) into buf (c&1)
    auto stage = [&](int c) {
        const uint32_t sb = smb + AST_BASE + (uint32_t)(c & 1) * AST_SIZE;
        const int kv0 = c * 32;
        const size_t kvrow0 = (size_t)(b * LKV + kv0);
        {
            int row = tid >> 3, c16 = tid & 7;       // 32 rows x 8 c16 = 256
            size_t off = (kvrow0 + row) * KVSTR + h * HDIM + c16 * 8;
            uint32_t d = swz(row, c16);
            cp16(sb + AST_KH + d, KVh + off);
            cp16(sb + AST_KL + d, KVl + off);
            cp16(sb + AST_VH + d, KVh + off + DIMC);
            cp16(sb + AST_VL + d, KVl + off + DIMC);
        }
#pragma unroll
        for (int jj = 0; jj < 4; jj++) {              // pos: 128 rows x 8 c16
            int i = tid + jj * 256;
            int row = i >> 3, c16 = i & 7;
            cp16(sb + AST_P + row * 144 + c16 * 16, posbase + (size_t)row * LKV + kv0 + c16 * 4);
        }
        CP_COMMIT();
    };

    float O[8][4];
#pragma unroll
    for (int nt = 0; nt < 8; nt++)
#pragma unroll
        for (int j = 0; j < 4; j++) O[nt][j] = 0.f;
    float mv0 = -1e30f, mv1 = -1e30f, l0 = 0.f, l1 = 0.f;

    stage(0);

    const int NT = LKV / 32;   // 32 tiles
    for (int c = 0; c < NT; ++c) {
        __syncthreads();
        if (c + 1 < NT) {
            stage(c + 1);
            asm volatile("cp.async.wait_group 1;" ::: "memory");
        } else {
            asm volatile("cp.async.wait_group 0;" ::: "memory");
        }
        __syncthreads();

        const uint32_t sb = smb + AST_BASE + (uint32_t)(c & 1) * AST_SIZE;

        // init S accumulator with 8*pos
        float acc[4][4];
        {
            const char* pB = sm + AST_BASE + (size_t)(c & 1) * AST_SIZE + AST_P
                           + (wid * 16 + er) * 144 + ec * 4;
#pragma unroll
            for (int nt = 0; nt < 4; nt++) {
                float2 p0 = *(const float2*)(pB + nt * 32);
                float2 p1 = *(const float2*)(pB + nt * 32 + 8 * 144);
                acc[nt][0] = 8.f * p0.x; acc[nt][1] = 8.f * p0.y;
                acc[nt][2] = 8.f * p1.x; acc[nt][3] = 8.f * p1.y;
            }
        }

        // S = Q K^T (3-pass split)
        {
            const uint32_t qbh = smb + AQ_H, qbl = smb + AQ_L;
            const uint32_t kbh = sb + AST_KH, kbl = sb + AST_KL;
#pragma unroll
            for (int ks = 0; ks < 4; ks++) {
                uint32_t qf_h[4], qf_l[4], kh[2][4], kl[2][4];
                ldsm4(qf_h, qbh + swz(wid * 16 + arl, ks * 2 + acs));
                ldsm4(qf_l, qbl + swz(wid * 16 + arl, ks * 2 + acs));
#pragma unroll
                for (int p = 0; p < 2; p++) {
                    ldsm4(kh[p], kbh + swz(p * 16 + brl, ks * 2 + bcs));
                    ldsm4(kl[p], kbl + swz(p * 16 + brl, ks * 2 + bcs));
                }
#pragma unroll
                for (int nt = 0; nt < 4; nt++)
                    mma16816(acc[nt], qf_h, &kh[nt >> 1][(nt & 1) * 2]);
#pragma unroll
                for (int nt = 0; nt < 4; nt++)
                    mma16816(acc[nt], qf_h, &kl[nt >> 1][(nt & 1) * 2]);
#pragma unroll
                for (int nt = 0; nt < 4; nt++)
                    mma16816(acc[nt], qf_l, &kh[nt >> 1][(nt & 1) * 2]);
            }
        }

        // online softmax on fragments
        float tmax0 = mv0, tmax1 = mv1;
#pragma unroll
        for (int nt = 0; nt < 4; nt++) {
            acc[nt][0] *= SCALE; acc[nt][1] *= SCALE;
            acc[nt][2] *= SCALE; acc[nt][3] *= SCALE;
            tmax0 = fmaxf(tmax0, fmaxf(acc[nt][0], acc[nt][1]));
            tmax1 = fmaxf(tmax1, fmaxf(acc[nt][2], acc[nt][3]));
        }
        tmax0 = fmaxf(tmax0, __shfl_xor_sync(0xffffffffu, tmax0, 1));
        tmax0 = fmaxf(tmax0, __shfl_xor_sync(0xffffffffu, tmax0, 2));
        tmax1 = fmaxf(tmax1, __shfl_xor_sync(0xffffffffu, tmax1, 1));
        tmax1 = fmaxf(tmax1, __shfl_xor_sync(0xffffffffu, tmax1, 2));

        float alpha0 = __expf(mv0 - tmax0);
        float alpha1 = __expf(mv1 - tmax1);
        mv0 = tmax0; mv1 = tmax1;

        uint32_t pa_h[2][4], pa_l[2][4];
        float la0 = 0.f, la1 = 0.f;
#pragma unroll
        for (int nt = 0; nt < 4; nt++) {
            float p0 = __expf(acc[nt][0] - mv0);
            float p1 = __expf(acc[nt][1] - mv0);
            float p2 = __expf(acc[nt][2] - mv1);
            float p3 = __expf(acc[nt][3] - mv1);
            la0 += p0 + p1; la1 += p2 + p3;
            __nv_bfloat162 h01 = __floats2bfloat162_rn(p0, p1);
            __nv_bfloat162 h23 = __floats2bfloat162_rn(p2, p3);
            float q0f = p0 - __low2float(h01), q1f = p1 - __high2float(h01);
            float q2f = p2 - __low2float(h23), q3f = p3 - __high2float(h23);
            int t = nt >> 1, base = (nt & 1) * 2;
            pa_h[t][base + 0] = *(uint32_t*)&h01;
            pa_h[t][base + 1] = *(uint32_t*)&h23;
            pa_l[t][base + 0] = packbf(q0f, q1f);
            pa_l[t][base + 1] = packbf(q2f, q3f);
        }
        l0 = l0 * alpha0 + la0;
        l1 = l1 * alpha1 + la1;

#pragma unroll
        for (int nt = 0; nt < 8; nt++) {
            O[nt][0] *= alpha0; O[nt][1] *= alpha0;
            O[nt][2] *= alpha1; O[nt][3] *= alpha1;
        }

        // O += P V (3-pass split), V via trans ldmatrix, consumed per-tp
        {
            const uint32_t vbh = sb + AST_VH, vbl = sb + AST_VL;
#pragma unroll
            for (int ks = 0; ks < 2; ks++) {
#pragma unroll
                for (int tp = 0; tp < 4; tp++) {
                    uint32_t vh[4], vl[4];
                    ldsm4t(vh, vbh + swz(ks * 16 + arl, tp * 2 + acs));
                    ldsm4t(vl, vbl + swz(ks * 16 + arl, tp * 2 + acs));
                    mma16816(O[tp * 2 + 0], pa_h[ks], &vh[0]);
                    mma16816(O[tp * 2 + 1], pa_h[ks], &vh[2]);
                    mma16816(O[tp * 2 + 0], pa_h[ks], &vl[0]);
                    mma16816(O[tp * 2 + 1], pa_h[ks], &vl[2]);
                    mma16816(O[tp * 2 + 0], pa_l[ks], &vh[0]);
                    mma16816(O[tp * 2 + 1], pa_l[ks], &vh[2]);
                }
            }
        }
    }

    l0 += __shfl_xor_sync(0xffffffffu, l0, 1);
    l0 += __shfl_xor_sync(0xffffffffu, l0, 2);
    l1 += __shfl_xor_sync(0xffffffffu, l1, 1);
    l1 += __shfl_xor_sync(0xffffffffu, l1, 2);
    float inv0 = 1.f / l0, inv1 = 1.f / l1;

    const size_t row0 = (size_t)(b * LQ + q0 + wid * 16 + er);
#pragma unroll
    for (int nt = 0; nt < 8; nt++) {
        int col = h * HDIM + nt * 8 + ec;
        float v0 = O[nt][0] * inv0, v1 = O[nt][1] * inv0;
        float v2 = O[nt][2] * inv1, v3 = O[nt][3] * inv1;
        __nv_bfloat162 h01 = __floats2bfloat162_rn(v0, v1);
        __nv_bfloat162 h23 = __floats2bfloat162_rn(v2, v3);
        float q0f = v0 - __low2float(h01), q1f = v1 - __high2float(h01);
        float q2f = v2 - __low2float(h23), q3f = v3 - __high2float(h23);
        size_t offA = row0 * DIMC + col;
        size_t offB = (row0 + 8) * DIMC + col;
        *(uint32_t*)(Oh + offA) = *(uint32_t*)&h01;
        *(uint32_t*)(Ol + offA) = packbf(q0f, q1f);
        *(uint32_t*)(Oh + offB) = *(uint32_t*)&h23;
        *(uint32_t*)(Ol + offB) = packbf(q2f, q3f);
    }
}

// ---------------------------------------------------------------------------
extern "C" void kernel_launch(void* const* d_in, const int* in_sizes, int n_in,
                              void* d_out, int out_size)
{
    (void)in_sizes; (void)n_in; (void)out_size;
    const float* q     = (const float*)d_in[0];
    const float* kv    = (const float*)d_in[1];
    const float* pos   = (const float*)d_in[2];
    const float* Wq    = (const float*)d_in[3];
    const float* Wkv   = (const float*)d_in[4];
    const float* Wproj = (const float*)d_in[5];
    const float* bproj = (const float*)d_in[6];
    float* out = (float*)d_out;

    __nv_bfloat16 *qh, *ql, *kvh, *kvl, *wqh, *wql, *wkh, *wkl, *wph, *wpl;
    __nv_bfloat16 *PQh, *PQl, *PKh, *PKl, *oh, *ol;
    cudaGetSymbolAddress((void**)&qh,  g_qh);   cudaGetSymbolAddress((void**)&ql,  g_ql);
    cudaGetSymbolAddress((void**)&kvh, g_kvh);  cudaGetSymbolAddress((void**)&kvl, g_kvl);
    cudaGetSymbolAddress((void**)&wqh, g_wqh);  cudaGetSymbolAddress((void**)&wql, g_wql);
    cudaGetSymbolAddress((void**)&wkh, g_wkh);  cudaGetSymbolAddress((void**)&wkl, g_wkl);
    cudaGetSymbolAddress((void**)&wph, g_wph);  cudaGetSymbolAddress((void**)&wpl, g_wpl);
    cudaGetSymbolAddress((void**)&PQh, g_PQh);  cudaGetSymbolAddress((void**)&PQl, g_PQl);
    cudaGetSymbolAddress((void**)&PKh, g_PKh);  cudaGetSymbolAddress((void**)&PKl, g_PKl);
    cudaGetSymbolAddress((void**)&oh,  g_oh);   cudaGetSymbolAddress((void**)&ol,  g_ol);

    static bool attr_done = false;
    if (!attr_done) {
        cudaFuncSetAttribute(gemm_qkv,  cudaFuncAttributeMaxDynamicSharedMemorySize, GEMM_SMEM);
        cudaFuncSetAttribute(gemm_proj, cudaFuncAttributeMaxDynamicSharedMemorySize, GEMM_SMEM);
        cudaFuncSetAttribute(attn_mma,  cudaFuncAttributeMaxDynamicSharedMemorySize, ATTN_SMEM);
        attr_done = true;
    }

    // one merged split kernel for all fp32 inputs
    {
        int grid = (int)((N4_TOT + 255) / 256);
        cvt_all<<<grid, 256>>>(
            (const float4*)q,   (uint2*)qh,  (uint2*)ql,
            (const float4*)kv,  (uint2*)kvh, (uint2*)kvl,
            (const float4*)Wq,  (uint2*)wqh, (uint2*)wql,
            (const float4*)Wkv, (uint2*)wkh, (uint2*)wkl,
            (const float4*)Wproj, (uint2*)wph, (uint2*)wpl);
    }

    // combined Q + KV projections -> split bf16
    gemm_qkv<<<2304, 256, GEMM_SMEM>>>(qh, ql, wqh, wql, PQh, PQl,
                                       kvh, kvl, wkh, wkl, PKh, PKl);

    // tensor-core flash attention -> split bf16 O
    attn_mma<<<dim3(LQ / 128, NHEADS, BATCH), 256, ATTN_SMEM>>>(
        PQh, PQl, PKh, PKl, pos, oh, ol);

    // output projection (fp32 + bias)
    gemm_proj<<<768, 256, GEMM_SMEM>>>(oh, ol, wph, wpl, bproj, out);
}

// round 11
// speedup vs baseline: 1.0416x; 1.0416x over previous
#include <cuda_runtime.h>
#include <cuda_bf16.h>
#include <cstdint>
#include <cstddef>

// Problem constants
#define DIMC   768
#define NHEADS 12
#define HDIM   64
#define BATCH  8
#define LQ     1024
#define LKV    1024
#define SCALE  0.125f
#define KVSTR  (2 * DIMC)       // 1536 (elements)

#define MROWS  (BATCH * LQ)     // 8192

// bf16 split scratch
__device__ __nv_bfloat16 g_qh  [(size_t)MROWS * DIMC];
__device__ __nv_bfloat16 g_ql  [(size_t)MROWS * DIMC];
__device__ __nv_bfloat16 g_kvh [(size_t)MROWS * DIMC];
__device__ __nv_bfloat16 g_kvl [(size_t)MROWS * DIMC];
__device__ __nv_bfloat16 g_wqh [(size_t)DIMC * DIMC];
__device__ __nv_bfloat16 g_wql [(size_t)DIMC * DIMC];
__device__ __nv_bfloat16 g_wkh [(size_t)2 * DIMC * DIMC];
__device__ __nv_bfloat16 g_wkl [(size_t)2 * DIMC * DIMC];
__device__ __nv_bfloat16 g_wph [(size_t)DIMC * DIMC];
__device__ __nv_bfloat16 g_wpl [(size_t)DIMC * DIMC];
__device__ __nv_bfloat16 g_PQh [(size_t)MROWS * DIMC];
__device__ __nv_bfloat16 g_PQl [(size_t)MROWS * DIMC];
__device__ __nv_bfloat16 g_PKh [(size_t)MROWS * 2 * DIMC];
__device__ __nv_bfloat16 g_PKl [(size_t)MROWS * 2 * DIMC];
__device__ __nv_bfloat16 g_oh  [(size_t)MROWS * DIMC];
__device__ __nv_bfloat16 g_ol  [(size_t)MROWS * DIMC];

// ---------------------------------------------------------------------------
__device__ __forceinline__ uint32_t smem_u32(const void* p) {
    uint32_t a;
    asm("{ .reg .u64 t; cvta.to.shared.u64 t, %1; cvt.u32.u64 %0, t; }" : "=r"(a) : "l"(p));
    return a;
}
__device__ __forceinline__ void ldsm4(uint32_t* r, uint32_t addr) {
    asm volatile("ldmatrix.sync.aligned.m8n8.x4.shared.b16 {%0,%1,%2,%3}, [%4];"
        : "=r"(r[0]), "=r"(r[1]), "=r"(r[2]), "=r"(r[3]) : "r"(addr));
}
__device__ __forceinline__ void ldsm4t(uint32_t* r, uint32_t addr) {
    asm volatile("ldmatrix.sync.aligned.m8n8.x4.trans.shared.b16 {%0,%1,%2,%3}, [%4];"
        : "=r"(r[0]), "=r"(r[1]), "=r"(r[2]), "=r"(r[3]) : "r"(addr));
}
__device__ __forceinline__ void mma16816(float* d, const uint32_t* a, const uint32_t* b) {
    asm volatile("mma.sync.aligned.m16n8k16.row.col.f32.bf16.bf16.f32 "
        "{%0,%1,%2,%3}, {%4,%5,%6,%7}, {%8,%9}, {%0,%1,%2,%3};"
        : "+f"(d[0]), "+f"(d[1]), "+f"(d[2]), "+f"(d[3])
        : "r"(a[0]), "r"(a[1]), "r"(a[2]), "r"(a[3]), "r"(b[0]), "r"(b[1]));
}
__device__ __forceinline__ void cp16(uint32_t dst, const void* src) {
    asm volatile("cp.async.cg.shared.global [%0], [%1], 16;" :: "r"(dst), "l"(src) : "memory");
}
#define CP_COMMIT() asm volatile("cp.async.commit_group;" ::: "memory")

__device__ __forceinline__ uint32_t packbf(float a, float b) {
    __nv_bfloat162 t = __floats2bfloat162_rn(a, b);
    return *(uint32_t*)&t;
}

// swizzled byte offset inside a 128B-row tile
__device__ __forceinline__ uint32_t swz(int row, int c16) {
    return (uint32_t)(row * 128 + ((c16 ^ (row & 7)) << 4));
}

// ---------------------------------------------------------------------------
// GEMM (R8 config): tile 128(M)x64(N), 256 threads, warp 32x32 (4x2 grid),
// K-chunks of 64, 2-stage cp.async, 2 CTAs/SM.
// ---------------------------------------------------------------------------
#define GSTG   49152          // AH 16K | AL 16K | WH 8K | WL 8K
#define GB_AH  0
#define GB_AL  16384
#define GB_WH  32768
#define GB_WL  40960
#define GEMM_SMEM (2 * GSTG)  // 98304

// stage A chunk: 128 rows x 64 bf16 = 1024 16B lines (4/thread)
__device__ __forceinline__ void stageA(uint32_t sdst, const __nv_bfloat16* rowbase,
                                       int K, int k0, int tid) {
#pragma unroll
    for (int rep = 0; rep < 4; rep++) {
        int i = tid + rep * 256;
        int row = i >> 3, c16 = i & 7;
        cp16(sdst + swz(row, c16), rowbase + (size_t)row * K + k0 + c16 * 8);
    }
}
// stage W chunk: 64 rows x 64 bf16 = 512 16B lines (2/thread)
__device__ __forceinline__ void stageW(uint32_t sdst, const __nv_bfloat16* rowbase,
                                       int K, int k0, int tid) {
#pragma unroll
    for (int rep = 0; rep < 2; rep++) {
        int i = tid + rep * 256;
        int row = i >> 3, c16 = i & 7;
        cp16(sdst + swz(row, c16), rowbase + (size_t)row * K + k0 + c16 * 8);
    }
}

__device__ __forceinline__
void gemm_body(const __nv_bfloat16* __restrict__ Ah, const __nv_bfloat16* __restrict__ Al,
               const __nv_bfloat16* __restrict__ Wh, const __nv_bfloat16* __restrict__ Wl,
               const float* __restrict__ bias, float* __restrict__ C,
               __nv_bfloat16* __restrict__ Ch, __nv_bfloat16* __restrict__ Cl,
               int N, int K, int m0, int n0, char* sm)
{
    const uint32_t smb = smem_u32(sm);
    const int tid = threadIdx.x;
    const int wid = tid >> 5, lane = tid & 31;
    const int wm = wid >> 1, wn = wid & 1;          // 4x2 warp grid, warp = 32x32

    const __nv_bfloat16* Ahb = Ah + (size_t)m0 * K;
    const __nv_bfloat16* Alb = Al + (size_t)m0 * K;
    const __nv_bfloat16* Whb = Wh + (size_t)n0 * K;
    const __nv_bfloat16* Wlb = Wl + (size_t)n0 * K;

    const int g = lane >> 3, r = lane & 7;
    const int arl = (g & 1) * 8 + r;
    const int acs = g >> 1;
    const int brl = (g >> 1) * 8 + r;
    const int bcs = g & 1;

    float acc[2][4][4];
#pragma unroll
    for (int i = 0; i < 2; i++)
#pragma unroll
        for (int j = 0; j < 4; j++)
#pragma unroll
            for (int k = 0; k < 4; k++) acc[i][j][k] = 0.f;

    const int NC = K >> 6;   // 12

    {
        uint32_t sb = smb;
        stageA(sb + GB_AH, Ahb, K, 0, tid);
        stageA(sb + GB_AL, Alb, K, 0, tid);
        stageW(sb + GB_WH, Whb, K, 0, tid);
        stageW(sb + GB_WL, Wlb, K, 0, tid);
        CP_COMMIT();
    }

    for (int c = 0; c < NC; ++c) {
        if (c + 1 < NC) {
            uint32_t sb = smb + ((c + 1) & 1) * GSTG;
            int k0 = (c + 1) << 6;
            stageA(sb + GB_AH, Ahb, K, k0, tid);
            stageA(sb + GB_AL, Alb, K, k0, tid);
            stageW(sb + GB_WH, Whb, K, k0, tid);
            stageW(sb + GB_WL, Wlb, K, k0, tid);
            CP_COMMIT();
            asm volatile("cp.async.wait_group 1;" ::: "memory");
        } else {
            asm volatile("cp.async.wait_group 0;" ::: "memory");
        }
        __syncthreads();

        const uint32_t sb = smb + (c & 1) * GSTG;
        const uint32_t bAh = sb + GB_AH, bAl = sb + GB_AL;
        const uint32_t bWh = sb + GB_WH, bWl = sb + GB_WL;

#pragma unroll
        for (int s = 0; s < 4; ++s) {
            uint32_t ah[2][4], al[2][4], bh[2][4], bl[2][4];
#pragma unroll
            for (int mt = 0; mt < 2; ++mt) {
                ldsm4(ah[mt], bAh + swz(wm * 32 + mt * 16 + arl, s * 2 + acs));
                ldsm4(al[mt], bAl + swz(wm * 32 + mt * 16 + arl, s * 2 + acs));
            }
#pragma unroll
            for (int p = 0; p < 2; ++p) {
                ldsm4(bh[p], bWh + swz(wn * 32 + p * 16 + brl, s * 2 + bcs));
                ldsm4(bl[p], bWl + swz(wn * 32 + p * 16 + brl, s * 2 + bcs));
            }
#pragma unroll
            for (int mt = 0; mt < 2; ++mt)
#pragma unroll
                for (int nt = 0; nt < 4; ++nt)
                    mma16816(acc[mt][nt], ah[mt], &bh[nt >> 1][(nt & 1) * 2]);
#pragma unroll
            for (int mt = 0; mt < 2; ++mt)
#pragma unroll
                for (int nt = 0; nt < 4; ++nt)
                    mma16816(acc[mt][nt], ah[mt], &bl[nt >> 1][(nt & 1) * 2]);
#pragma unroll
            for (int mt = 0; mt < 2; ++mt)
#pragma unroll
                for (int nt = 0; nt < 4; ++nt)
                    mma16816(acc[mt][nt], al[mt], &bh[nt >> 1][(nt & 1) * 2]);
        }
        __syncthreads();
    }

    const int er = lane >> 2, ec = (lane & 3) * 2;
    if (Ch) {
#pragma unroll
        for (int mt = 0; mt < 2; ++mt) {
#pragma unroll
            for (int nt = 0; nt < 4; ++nt) {
                int grow = m0 + wm * 32 + mt * 16 + er;
                int gcol = n0 + wn * 32 + nt * 8 + ec;
#pragma unroll
                for (int rr = 0; rr < 2; ++rr) {
                    float v0 = acc[mt][nt][rr * 2 + 0];
                    float v1 = acc[mt][nt][rr * 2 + 1];
                    __nv_bfloat16 h0 = __float2bfloat16_rn(v0);
                    __nv_bfloat16 h1 = __float2bfloat16_rn(v1);
                    float l0f = v0 - __bfloat162float(h0);
                    float l1f = v1 - __bfloat162float(h1);
                    size_t off = (size_t)(grow + rr * 8) * N + gcol;
                    *(uint32_t*)(Ch + off) = packbf(__bfloat162float(h0), __bfloat162float(h1));
                    *(uint32_t*)(Cl + off) = packbf(l0f, l1f);
                }
            }
        }
    } else {
#pragma unroll
        for (int mt = 0; mt < 2; ++mt) {
#pragma unroll
            for (int nt = 0; nt < 4; ++nt) {
                int grow = m0 + wm * 32 + mt * 16 + er;
                int gcol = n0 + wn * 32 + nt * 8 + ec;
                float b0 = 0.f, b1 = 0.f;
                if (bias) { b0 = bias[gcol]; b1 = bias[gcol + 1]; }
                float2 v0 = make_float2(acc[mt][nt][0] + b0, acc[mt][nt][1] + b1);
                float2 v1 = make_float2(acc[mt][nt][2] + b0, acc[mt][nt][3] + b1);
                *(float2*)(C + (size_t)grow * N + gcol) = v0;
                *(float2*)(C + (size_t)(grow + 8) * N + gcol) = v1;
            }
        }
    }
}

// Combined Q + KV projection gemm.
__global__ __launch_bounds__(256, 2)
void gemm_qkv(const __nv_bfloat16* __restrict__ qh, const __nv_bfloat16* __restrict__ ql,
              const __nv_bfloat16* __restrict__ wqh, const __nv_bfloat16* __restrict__ wql,
              __nv_bfloat16* __restrict__ PQh, __nv_bfloat16* __restrict__ PQl,
              const __nv_bfloat16* __restrict__ kvh, const __nv_bfloat16* __restrict__ kvl,
              const __nv_bfloat16* __restrict__ wkh, const __nv_bfloat16* __restrict__ wkl,
              __nv_bfloat16* __restrict__ PKh, __nv_bfloat16* __restrict__ PKl)
{
    extern __shared__ char sm[];
    int bx = blockIdx.x;
    if (bx < 768) {
        int nb = bx % 12, mb = bx / 12;
        gemm_body(qh, ql, wqh, wql, nullptr, nullptr, PQh, PQl,
                  DIMC, DIMC, mb * 128, nb * 64, sm);
    } else {
        int t = bx - 768;
        int nb = t % 24, mb = t / 24;
        gemm_body(kvh, kvl, wkh, wkl, nullptr, nullptr, PKh, PKl,
                  2 * DIMC, DIMC, mb * 128, nb * 64, sm);
    }
}

// Output projection gemm (fp32 out + bias).
__global__ __launch_bounds__(256, 2)
void gemm_proj(const __nv_bfloat16* __restrict__ oh, const __nv_bfloat16* __restrict__ ol,
               const __nv_bfloat16* __restrict__ wph, const __nv_bfloat16* __restrict__ wpl,
               const float* __restrict__ bias, float* __restrict__ out)
{
    extern __shared__ char sm[];
    int nb = blockIdx.x % 12, mb = blockIdx.x / 12;
    gemm_body(oh, ol, wph, wpl, bias, out, nullptr, nullptr,
              DIMC, DIMC, mb * 128, nb * 64, sm);
}

// ---------------------------------------------------------------------------
// One merged fp32 -> (hi,lo) bf16 split over all 5 input arrays.
// ---------------------------------------------------------------------------
#define N4_Q   ((size_t)MROWS * DIMC / 4)
#define N4_W1  ((size_t)DIMC * DIMC / 4)
#define N4_W2  ((size_t)2 * DIMC * DIMC / 4)
#define N4_TOT (N4_Q + N4_Q + N4_W1 + N4_W2 + N4_W1)

__global__ __launch_bounds__(256)
void cvt_all(const float4* __restrict__ q,   uint2* __restrict__ qh,  uint2* __restrict__ ql,
             const float4* __restrict__ kv,  uint2* __restrict__ kvh, uint2* __restrict__ kvl,
             const float4* __restrict__ wq,  uint2* __restrict__ wqh, uint2* __restrict__ wql,
             const float4* __restrict__ wkv, uint2* __restrict__ wkh, uint2* __restrict__ wkl,
             const float4* __restrict__ wp,  uint2* __restrict__ wph, uint2* __restrict__ wpl)
{
    size_t i = (size_t)blockIdx.x * blockDim.x + threadIdx.x;
    if (i >= N4_TOT) return;
    const float4* src; uint2 *hi, *lo; size_t j = i;
    if (j < N4_Q)                 { src = q;   hi = qh;  lo = ql;  }
    else if ((j -= N4_Q) < N4_Q)  { src = kv;  hi = kvh; lo = kvl; }
    else if ((j -= N4_Q) < N4_W1) { src = wq;  hi = wqh; lo = wql; }
    else if ((j -= N4_W1) < N4_W2){ src = wkv; hi = wkh; lo = wkl; }
    else { j -= N4_W2;              src = wp;  hi = wph; lo = wpl; }

    float4 x = src[j];
    __nv_bfloat162 h01 = __floats2bfloat162_rn(x.x, x.y);
    __nv_bfloat162 h23 = __floats2bfloat162_rn(x.z, x.w);
    float r0 = x.x - __low2float(h01), r1 = x.y - __high2float(h01);
    float r2 = x.z - __low2float(h23), r3 = x.w - __high2float(h23);
    __nv_bfloat162 l01 = __floats2bfloat162_rn(r0, r1);
    __nv_bfloat162 l23 = __floats2bfloat162_rn(r2, r3);
    hi[j] = make_uint2(*(uint32_t*)&h01, *(uint32_t*)&h23);
    lo[j] = make_uint2(*(uint32_t*)&l01, *(uint32_t*)&l23);
}

// ---------------------------------------------------------------------------
// Tensor-core flash attention, bf16-split. kv-tile 64, pos via registers,
// 2 CTAs/SM. smem: Qh|Ql (32KB) + 2 stages { KH,KL,VH,VL 8KB each } = 96KB
// ---------------------------------------------------------------------------
#define AQ_H     0
#define AQ_L     16384
#define AST_BASE 32768
#define AST_KH   0
#define AST_KL   8192
#define AST_VH   16384
#define AST_VL   24576
#define AST_SIZE 32768
#define ATTN_SMEM (AST_BASE + 2 * AST_SIZE)   // 98304

__global__ __launch_bounds__(256, 2)
void attn_mma(const __nv_bfloat16* __restrict__ Qh, const __nv_bfloat16* __restrict__ Ql,
              const __nv_bfloat16* __restrict__ KVh, const __nv_bfloat16* __restrict__ KVl,
              const float* __restrict__ pos,
              __nv_bfloat16* __restrict__ Oh, __nv_bfloat16* __restrict__ Ol)
{
    extern __shared__ char sm[];
    const uint32_t smb = smem_u32(sm);
    const int tid = threadIdx.x, wid = tid >> 5, lane = tid & 31;
    const int b = blockIdx.z, h = blockIdx.y;
    const int q0 = blockIdx.x * 128;

    const int g = lane >> 3, r = lane & 7;
    const int arl = (g & 1) * 8 + r, acs = g >> 1;
    const int brl = (g >> 1) * 8 + r, bcs = g & 1;
    const int er = lane >> 2, ec = (lane & 3) * 2;

    // stage Q tile (hi/lo) once: 128 rows x 64 bf16 each
    const size_t qrow0 = (size_t)(b * LQ + q0);
    for (int i = tid; i < 128 * 8; i += 256) {
        int row = i >> 3, c16 = i & 7;
        size_t off = (qrow0 + row) * DIMC + h * HDIM + c16 * 8;
        uint32_t d = swz(row, c16);
        cp16(smb + AQ_H + d, Qh + off);
        cp16(smb + AQ_L + d, Ql + off);
    }
    CP_COMMIT();

    // per-thread pos base: this thread owns rows (wid*16+er, +8), cols ec + nt*8
    const float* pb0 = pos + ((size_t)(h * LQ + q0 + wid * 16 + er)) * LKV + ec;
    const float* pb1 = pb0 + (size_t)8 * LKV;

    // stage kv tile c (K/V hi/lo only) into buf (c&1)
    auto stage = [&](int c) {
        const uint32_t sb = smb + AST_BASE + (uint32_t)(c & 1) * AST_SIZE;
        const int kv0 = c * 64;
        const size_t kvrow0 = (size_t)(b * LKV + kv0);
#pragma unroll
        for (int jj = 0; jj < 2; jj++) {
            int i = tid + jj * 256;                  // 64 rows x 8 c16 = 512
            int row = i >> 3, c16 = i & 7;
            size_t off = (kvrow0 + row) * KVSTR + h * HDIM + c16 * 8;
            uint32_t d = swz(row, c16);
            cp16(sb + AST_KH + d, KVh + off);
            cp16(sb + AST_KL + d, KVl + off);
            cp16(sb + AST_VH + d, KVh + off + DIMC);
            cp16(sb + AST_VL + d, KVl + off + DIMC);
        }
        CP_COMMIT();
    };

    float O[8][4];
#pragma unroll
    for (int nt = 0; nt < 8; nt++)
#pragma unroll
        for (int j = 0; j < 4; j++) O[nt][j] = 0.f;
    float mv0 = -1e30f, mv1 = -1e30f, l0 = 0.f, l1 = 0.f;

    // prefetch pos for tile 0 into registers
    float pacc[8][4];
#pragma unroll
    for (int nt = 0; nt < 8; nt++) {
        float2 p0 = *(const float2*)(pb0 + nt * 8);
        float2 p1 = *(const float2*)(pb1 + nt * 8);
        pacc[nt][0] = p0.x; pacc[nt][1] = p0.y;
        pacc[nt][2] = p1.x; pacc[nt][3] = p1.y;
    }

    stage(0);

    const int NT = LKV / 64;   // 16
    for (int c = 0; c < NT; ++c) {
        __syncthreads();
        if (c + 1 < NT) {
            stage(c + 1);
            asm volatile("cp.async.wait_group 1;" ::: "memory");
        } else {
            asm volatile("cp.async.wait_group 0;" ::: "memory");
        }
        __syncthreads();

        const uint32_t sb = smb + AST_BASE + (uint32_t)(c & 1) * AST_SIZE;

        // init S accumulator with 8*pos (final *SCALE gives QK*0.125 + pos)
        float acc[8][4];
#pragma unroll
        for (int nt = 0; nt < 8; nt++) {
            acc[nt][0] = 8.f * pacc[nt][0]; acc[nt][1] = 8.f * pacc[nt][1];
            acc[nt][2] = 8.f * pacc[nt][2]; acc[nt][3] = 8.f * pacc[nt][3];
        }

        // S = Q K^T (3-pass split); K frags consumed per-p to limit registers
        {
            const uint32_t qbh = smb + AQ_H, qbl = smb + AQ_L;
            const uint32_t kbh = sb + AST_KH, kbl = sb + AST_KL;
#pragma unroll
            for (int ks = 0; ks < 4; ks++) {
                uint32_t qf_h[4], qf_l[4];
                ldsm4(qf_h, qbh + swz(wid * 16 + arl, ks * 2 + acs));
                ldsm4(qf_l, qbl + swz(wid * 16 + arl, ks * 2 + acs));
#pragma unroll
                for (int p = 0; p < 4; p++) {
                    uint32_t kh[4], kl[4];
                    ldsm4(kh, kbh + swz(p * 16 + brl, ks * 2 + bcs));
                    ldsm4(kl, kbl + swz(p * 16 + brl, ks * 2 + bcs));
                    mma16816(acc[p * 2 + 0], qf_h, &kh[0]);
                    mma16816(acc[p * 2 + 1], qf_h, &kh[2]);
                    mma16816(acc[p * 2 + 0], qf_h, &kl[0]);
                    mma16816(acc[p * 2 + 1], qf_h, &kl[2]);
                    mma16816(acc[p * 2 + 0], qf_l, &kh[0]);
                    mma16816(acc[p * 2 + 1], qf_l, &kh[2]);
                }
            }
        }

        // online softmax on fragments
        float tmax0 = mv0, tmax1 = mv1;
#pragma unroll
        for (int nt = 0; nt < 8; nt++) {
            acc[nt][0] *= SCALE; acc[nt][1] *= SCALE;
            acc[nt][2] *= SCALE; acc[nt][3] *= SCALE;
            tmax0 = fmaxf(tmax0, fmaxf(acc[nt][0], acc[nt][1]));
            tmax1 = fmaxf(tmax1, fmaxf(acc[nt][2], acc[nt][3]));
        }
        tmax0 = fmaxf(tmax0, __shfl_xor_sync(0xffffffffu, tmax0, 1));
        tmax0 = fmaxf(tmax0, __shfl_xor_sync(0xffffffffu, tmax0, 2));
        tmax1 = fmaxf(tmax1, __shfl_xor_sync(0xffffffffu, tmax1, 1));
        tmax1 = fmaxf(tmax1, __shfl_xor_sync(0xffffffffu, tmax1, 2));

        float alpha0 = __expf(mv0 - tmax0);
        float alpha1 = __expf(mv1 - tmax1);
        mv0 = tmax0; mv1 = tmax1;

        uint32_t pa_h[4][4], pa_l[4][4];
        float la0 = 0.f, la1 = 0.f;
#pragma unroll
        for (int nt = 0; nt < 8; nt++) {
            float p0 = __expf(acc[nt][0] - mv0);
            float p1 = __expf(acc[nt][1] - mv0);
            float p2 = __expf(acc[nt][2] - mv1);
            float p3 = __expf(acc[nt][3] - mv1);
            la0 += p0 + p1; la1 += p2 + p3;
            __nv_bfloat162 h01 = __floats2bfloat162_rn(p0, p1);
            __nv_bfloat162 h23 = __floats2bfloat162_rn(p2, p3);
            float q0f = p0 - __low2float(h01), q1f = p1 - __high2float(h01);
            float q2f = p2 - __low2float(h23), q3f = p3 - __high2float(h23);
            int t = nt >> 1, base = (nt & 1) * 2;
            pa_h[t][base + 0] = *(uint32_t*)&h01;
            pa_h[t][base + 1] = *(uint32_t*)&h23;
            pa_l[t][base + 0] = packbf(q0f, q1f);
            pa_l[t][base + 1] = packbf(q2f, q3f);
        }
        l0 = l0 * alpha0 + la0;
        l1 = l1 * alpha1 + la1;

#pragma unroll
        for (int nt = 0; nt < 8; nt++) {
            O[nt][0] *= alpha0; O[nt][1] *= alpha0;
            O[nt][2] *= alpha1; O[nt][3] *= alpha1;
        }

        // prefetch pos for tile c+1 into registers (acc is dead now; hides DRAM
        // latency under the PV mma below)
        if (c + 1 < NT) {
            const int off = (c + 1) * 64;
#pragma unroll
            for (int nt = 0; nt < 8; nt++) {
                float2 p0 = *(const float2*)(pb0 + off + nt * 8);
                float2 p1 = *(const float2*)(pb1 + off + nt * 8);
                pacc[nt][0] = p0.x; pacc[nt][1] = p0.y;
                pacc[nt][2] = p1.x; pacc[nt][3] = p1.y;
            }
        }

        // O += P V (3-pass split), V via trans ldmatrix, consumed per-tp
        {
            const uint32_t vbh = sb + AST_VH, vbl = sb + AST_VL;
#pragma unroll
            for (int ks = 0; ks < 4; ks++) {
#pragma unroll
                for (int tp = 0; tp < 4; tp++) {
                    uint32_t vh[4], vl[4];
                    ldsm4t(vh, vbh + swz(ks * 16 + arl, tp * 2 + acs));
                    ldsm4t(vl, vbl + swz(ks * 16 + arl, tp * 2 + acs));
                    mma16816(O[tp * 2 + 0], pa_h[ks], &vh[0]);
                    mma16816(O[tp * 2 + 1], pa_h[ks], &vh[2]);
                    mma16816(O[tp * 2 + 0], pa_h[ks], &vl[0]);
                    mma16816(O[tp * 2 + 1], pa_h[ks], &vl[2]);
                    mma16816(O[tp * 2 + 0], pa_l[ks], &vh[0]);
                    mma16816(O[tp * 2 + 1], pa_l[ks], &vh[2]);
                }
            }
        }
    }

    l0 += __shfl_xor_sync(0xffffffffu, l0, 1);
    l0 += __shfl_xor_sync(0xffffffffu, l0, 2);
    l1 += __shfl_xor_sync(0xffffffffu, l1, 1);
    l1 += __shfl_xor_sync(0xffffffffu, l1, 2);
    float inv0 = 1.f / l0, inv1 = 1.f / l1;

    const size_t row0 = (size_t)(b * LQ + q0 + wid * 16 + er);
#pragma unroll
    for (int nt = 0; nt < 8; nt++) {
        int col = h * HDIM + nt * 8 + ec;
        float v0 = O[nt][0] * inv0, v1 = O[nt][1] * inv0;
        float v2 = O[nt][2] * inv1, v3 = O[nt][3] * inv1;
        __nv_bfloat162 h01 = __floats2bfloat162_rn(v0, v1);
        __nv_bfloat162 h23 = __floats2bfloat162_rn(v2, v3);
        float q0f = v0 - __low2float(h01), q1f = v1 - __high2float(h01);
        float q2f = v2 - __low2float(h23), q3f = v3 - __high2float(h23);
        size_t offA = row0 * DIMC + col;
        size_t offB = (row0 + 8) * DIMC + col;
        *(uint32_t*)(Oh + offA) = *(uint32_t*)&h01;
        *(uint32_t*)(Ol + offA) = packbf(q0f, q1f);
        *(uint32_t*)(Oh + offB) = *(uint32_t*)&h23;
        *(uint32_t*)(Ol + offB) = packbf(q2f, q3f);
    }
}

// ---------------------------------------------------------------------------
extern "C" void kernel_launch(void* const* d_in, const int* in_sizes, int n_in,
                              void* d_out, int out_size)
{
    (void)in_sizes; (void)n_in; (void)out_size;
    const float* q     = (const float*)d_in[0];
    const float* kv    = (const float*)d_in[1];
    const float* pos   = (const float*)d_in[2];
    const float* Wq    = (const float*)d_in[3];
    const float* Wkv   = (const float*)d_in[4];
    const float* Wproj = (const float*)d_in[5];
    const float* bproj = (const float*)d_in[6];
    float* out = (float*)d_out;

    __nv_bfloat16 *qh, *ql, *kvh, *kvl, *wqh, *wql, *wkh, *wkl, *wph, *wpl;
    __nv_bfloat16 *PQh, *PQl, *PKh, *PKl, *oh, *ol;
    cudaGetSymbolAddress((void**)&qh,  g_qh);   cudaGetSymbolAddress((void**)&ql,  g_ql);
    cudaGetSymbolAddress((void**)&kvh, g_kvh);  cudaGetSymbolAddress((void**)&kvl, g_kvl);
    cudaGetSymbolAddress((void**)&wqh, g_wqh);  cudaGetSymbolAddress((void**)&wql, g_wql);
    cudaGetSymbolAddress((void**)&wkh, g_wkh);  cudaGetSymbolAddress((void**)&wkl, g_wkl);
    cudaGetSymbolAddress((void**)&wph, g_wph);  cudaGetSymbolAddress((void**)&wpl, g_wpl);
    cudaGetSymbolAddress((void**)&PQh, g_PQh);  cudaGetSymbolAddress((void**)&PQl, g_PQl);
    cudaGetSymbolAddress((void**)&PKh, g_PKh);  cudaGetSymbolAddress((void**)&PKl, g_PKl);
    cudaGetSymbolAddress((void**)&oh,  g_oh);   cudaGetSymbolAddress((void**)&ol,  g_ol);

    static bool attr_done = false;
    if (!attr_done) {
        cudaFuncSetAttribute(gemm_qkv,  cudaFuncAttributeMaxDynamicSharedMemorySize, GEMM_SMEM);
        cudaFuncSetAttribute(gemm_proj, cudaFuncAttributeMaxDynamicSharedMemorySize, GEMM_SMEM);
        cudaFuncSetAttribute(attn_mma,  cudaFuncAttributeMaxDynamicSharedMemorySize, ATTN_SMEM);
        attr_done = true;
    }

    // one merged split kernel for all fp32 inputs
    {
        int grid = (int)((N4_TOT + 255) / 256);
        cvt_all<<<grid, 256>>>(
            (const float4*)q,   (uint2*)qh,  (uint2*)ql,
            (const float4*)kv,  (uint2*)kvh, (uint2*)kvl,
            (const float4*)Wq,  (uint2*)wqh, (uint2*)wql,
            (const float4*)Wkv, (uint2*)wkh, (uint2*)wkl,
            (const float4*)Wproj, (uint2*)wph, (uint2*)wpl);
    }

    // combined Q + KV projections -> split bf16
    gemm_qkv<<<2304, 256, GEMM_SMEM>>>(qh, ql, wqh, wql, PQh, PQl,
                                       kvh, kvl, wkh, wkl, PKh, PKl);

    // tensor-core flash attention -> split bf16 O
    attn_mma<<<dim3(LQ / 128, NHEADS, BATCH), 256, ATTN_SMEM>>>(
        PQh, PQl, PKh, PKl, pos, oh, ol);

    // output projection (fp32 + bias)
    gemm_proj<<<768, 256, GEMM_SMEM>>>(oh, ol, wph, wpl, bproj, out);
}

// round 12
// speedup vs baseline: 1.0603x; 1.0179x over previous
#include <cuda_runtime.h>
#include <cuda_bf16.h>
#include <cstdint>
#include <cstddef>

// Problem constants
#define DIMC   768
#define NHEADS 12
#define HDIM   64
#define BATCH  8
#define LQ     1024
#define LKV    1024
#define SCALE  0.125f
#define KVSTR  (2 * DIMC)       // 1536 (elements)

#define MROWS  (BATCH * LQ)     // 8192

// bf16 split scratch
__device__ __nv_bfloat16 g_qh  [(size_t)MROWS * DIMC];
__device__ __nv_bfloat16 g_ql  [(size_t)MROWS * DIMC];
__device__ __nv_bfloat16 g_kvh [(size_t)MROWS * DIMC];
__device__ __nv_bfloat16 g_kvl [(size_t)MROWS * DIMC];
__device__ __nv_bfloat16 g_wqh [(size_t)DIMC * DIMC];
__device__ __nv_bfloat16 g_wql [(size_t)DIMC * DIMC];
__device__ __nv_bfloat16 g_wkh [(size_t)2 * DIMC * DIMC];
__device__ __nv_bfloat16 g_wkl [(size_t)2 * DIMC * DIMC];
__device__ __nv_bfloat16 g_wph [(size_t)DIMC * DIMC];
__device__ __nv_bfloat16 g_wpl [(size_t)DIMC * DIMC];
__device__ __nv_bfloat16 g_PQh [(size_t)MROWS * DIMC];
__device__ __nv_bfloat16 g_PQl [(size_t)MROWS * DIMC];
__device__ __nv_bfloat16 g_PKh [(size_t)MROWS * 2 * DIMC];
__device__ __nv_bfloat16 g_PKl [(size_t)MROWS * 2 * DIMC];
__device__ __nv_bfloat16 g_oh  [(size_t)MROWS * DIMC];
__device__ __nv_bfloat16 g_ol  [(size_t)MROWS * DIMC];

// ---------------------------------------------------------------------------
__device__ __forceinline__ uint32_t smem_u32(const void* p) {
    uint32_t a;
    asm("{ .reg .u64 t; cvta.to.shared.u64 t, %1; cvt.u32.u64 %0, t; }" : "=r"(a) : "l"(p));
    return a;
}
__device__ __forceinline__ void ldsm4(uint32_t* r, uint32_t addr) {
    asm volatile("ldmatrix.sync.aligned.m8n8.x4.shared.b16 {%0,%1,%2,%3}, [%4];"
        : "=r"(r[0]), "=r"(r[1]), "=r"(r[2]), "=r"(r[3]) : "r"(addr));
}
__device__ __forceinline__ void ldsm4t(uint32_t* r, uint32_t addr) {
    asm volatile("ldmatrix.sync.aligned.m8n8.x4.trans.shared.b16 {%0,%1,%2,%3}, [%4];"
        : "=r"(r[0]), "=r"(r[1]), "=r"(r[2]), "=r"(r[3]) : "r"(addr));
}
__device__ __forceinline__ void mma16816(float* d, const uint32_t* a, const uint32_t* b) {
    asm volatile("mma.sync.aligned.m16n8k16.row.col.f32.bf16.bf16.f32 "
        "{%0,%1,%2,%3}, {%4,%5,%6,%7}, {%8,%9}, {%0,%1,%2,%3};"
        : "+f"(d[0]), "+f"(d[1]), "+f"(d[2]), "+f"(d[3])
        : "r"(a[0]), "r"(a[1]), "r"(a[2]), "r"(a[3]), "r"(b[0]), "r"(b[1]));
}
__device__ __forceinline__ void cp16(uint32_t dst, const void* src) {
    asm volatile("cp.async.cg.shared.global [%0], [%1], 16;" :: "r"(dst), "l"(src) : "memory");
}
#define CP_COMMIT() asm volatile("cp.async.commit_group;" ::: "memory")

__device__ __forceinline__ uint32_t packbf(float a, float b) {
    __nv_bfloat162 t = __floats2bfloat162_rn(a, b);
    return *(uint32_t*)&t;
}

// swizzled byte offset inside a 128B-row tile
__device__ __forceinline__ uint32_t swz(int row, int c16) {
    return (uint32_t)(row * 128 + ((c16 ^ (row & 7)) << 4));
}

// ---------------------------------------------------------------------------
// GEMM (R8 config): tile 128(M)x64(N), 256 threads, warp 32x32 (4x2 grid),
// K-chunks of 64, 2-stage cp.async, 2 CTAs/SM.
// ---------------------------------------------------------------------------
#define GSTG   49152
#define GB_AH  0
#define GB_AL  16384
#define GB_WH  32768
#define GB_WL  40960
#define GEMM_SMEM (2 * GSTG)  // 98304

__device__ __forceinline__ void stageA(uint32_t sdst, const __nv_bfloat16* rowbase,
                                       int K, int k0, int tid) {
#pragma unroll
    for (int rep = 0; rep < 4; rep++) {
        int i = tid + rep * 256;
        int row = i >> 3, c16 = i & 7;
        cp16(sdst + swz(row, c16), rowbase + (size_t)row * K + k0 + c16 * 8);
    }
}
__device__ __forceinline__ void stageW(uint32_t sdst, const __nv_bfloat16* rowbase,
                                       int K, int k0, int tid) {
#pragma unroll
    for (int rep = 0; rep < 2; rep++) {
        int i = tid + rep * 256;
        int row = i >> 3, c16 = i & 7;
        cp16(sdst + swz(row, c16), rowbase + (size_t)row * K + k0 + c16 * 8);
    }
}

__device__ __forceinline__
void gemm_body(const __nv_bfloat16* __restrict__ Ah, const __nv_bfloat16* __restrict__ Al,
               const __nv_bfloat16* __restrict__ Wh, const __nv_bfloat16* __restrict__ Wl,
               const float* __restrict__ bias, float* __restrict__ C,
               __nv_bfloat16* __restrict__ Ch, __nv_bfloat16* __restrict__ Cl,
               int N, int K, int m0, int n0, char* sm)
{
    const uint32_t smb = smem_u32(sm);
    const int tid = threadIdx.x;
    const int wid = tid >> 5, lane = tid & 31;
    const int wm = wid >> 1, wn = wid & 1;

    const __nv_bfloat16* Ahb = Ah + (size_t)m0 * K;
    const __nv_bfloat16* Alb = Al + (size_t)m0 * K;
    const __nv_bfloat16* Whb = Wh + (size_t)n0 * K;
    const __nv_bfloat16* Wlb = Wl + (size_t)n0 * K;

    const int g = lane >> 3, r = lane & 7;
    const int arl = (g & 1) * 8 + r;
    const int acs = g >> 1;
    const int brl = (g >> 1) * 8 + r;
    const int bcs = g & 1;

    float acc[2][4][4];
#pragma unroll
    for (int i = 0; i < 2; i++)
#pragma unroll
        for (int j = 0; j < 4; j++)
#pragma unroll
            for (int k = 0; k < 4; k++) acc[i][j][k] = 0.f;

    const int NC = K >> 6;   // 12

    {
        uint32_t sb = smb;
        stageA(sb + GB_AH, Ahb, K, 0, tid);
        stageA(sb + GB_AL, Alb, K, 0, tid);
        stageW(sb + GB_WH, Whb, K, 0, tid);
        stageW(sb + GB_WL, Wlb, K, 0, tid);
        CP_COMMIT();
    }

    for (int c = 0; c < NC; ++c) {
        if (c + 1 < NC) {
            uint32_t sb = smb + ((c + 1) & 1) * GSTG;
            int k0 = (c + 1) << 6;
            stageA(sb + GB_AH, Ahb, K, k0, tid);
            stageA(sb + GB_AL, Alb, K, k0, tid);
            stageW(sb + GB_WH, Whb, K, k0, tid);
            stageW(sb + GB_WL, Wlb, K, k0, tid);
            CP_COMMIT();
            asm volatile("cp.async.wait_group 1;" ::: "memory");
        } else {
            asm volatile("cp.async.wait_group 0;" ::: "memory");
        }
        __syncthreads();

        const uint32_t sb = smb + (c & 1) * GSTG;
        const uint32_t bAh = sb + GB_AH, bAl = sb + GB_AL;
        const uint32_t bWh = sb + GB_WH, bWl = sb + GB_WL;

#pragma unroll
        for (int s = 0; s < 4; ++s) {
            uint32_t ah[2][4], al[2][4], bh[2][4], bl[2][4];
#pragma unroll
            for (int mt = 0; mt < 2; ++mt) {
                ldsm4(ah[mt], bAh + swz(wm * 32 + mt * 16 + arl, s * 2 + acs));
                ldsm4(al[mt], bAl + swz(wm * 32 + mt * 16 + arl, s * 2 + acs));
            }
#pragma unroll
            for (int p = 0; p < 2; ++p) {
                ldsm4(bh[p], bWh + swz(wn * 32 + p * 16 + brl, s * 2 + bcs));
                ldsm4(bl[p], bWl + swz(wn * 32 + p * 16 + brl, s * 2 + bcs));
            }
#pragma unroll
            for (int mt = 0; mt < 2; ++mt)
#pragma unroll
                for (int nt = 0; nt < 4; ++nt)
                    mma16816(acc[mt][nt], ah[mt], &bh[nt >> 1][(nt & 1) * 2]);
#pragma unroll
            for (int mt = 0; mt < 2; ++mt)
#pragma unroll
                for (int nt = 0; nt < 4; ++nt)
                    mma16816(acc[mt][nt], ah[mt], &bl[nt >> 1][(nt & 1) * 2]);
#pragma unroll
            for (int mt = 0; mt < 2; ++mt)
#pragma unroll
                for (int nt = 0; nt < 4; ++nt)
                    mma16816(acc[mt][nt], al[mt], &bh[nt >> 1][(nt & 1) * 2]);
        }
        __syncthreads();
    }

    const int er = lane >> 2, ec = (lane & 3) * 2;
    if (Ch) {
#pragma unroll
        for (int mt = 0; mt < 2; ++mt) {
#pragma unroll
            for (int nt = 0; nt < 4; ++nt) {
                int grow = m0 + wm * 32 + mt * 16 + er;
                int gcol = n0 + wn * 32 + nt * 8 + ec;
#pragma unroll
                for (int rr = 0; rr < 2; ++rr) {
                    float v0 = acc[mt][nt][rr * 2 + 0];
                    float v1 = acc[mt][nt][rr * 2 + 1];
                    __nv_bfloat16 h0 = __float2bfloat16_rn(v0);
                    __nv_bfloat16 h1 = __float2bfloat16_rn(v1);
                    float l0f = v0 - __bfloat162float(h0);
                    float l1f = v1 - __bfloat162float(h1);
                    size_t off = (size_t)(grow + rr * 8) * N + gcol;
                    *(uint32_t*)(Ch + off) = packbf(__bfloat162float(h0), __bfloat162float(h1));
                    *(uint32_t*)(Cl + off) = packbf(l0f, l1f);
                }
            }
        }
    } else {
#pragma unroll
        for (int mt = 0; mt < 2; ++mt) {
#pragma unroll
            for (int nt = 0; nt < 4; ++nt) {
                int grow = m0 + wm * 32 + mt * 16 + er;
                int gcol = n0 + wn * 32 + nt * 8 + ec;
                float b0 = 0.f, b1 = 0.f;
                if (bias) { b0 = bias[gcol]; b1 = bias[gcol + 1]; }
                float2 v0 = make_float2(acc[mt][nt][0] + b0, acc[mt][nt][1] + b1);
                float2 v1 = make_float2(acc[mt][nt][2] + b0, acc[mt][nt][3] + b1);
                *(float2*)(C + (size_t)grow * N + gcol) = v0;
                *(float2*)(C + (size_t)(grow + 8) * N + gcol) = v1;
            }
        }
    }
}

__global__ __launch_bounds__(256, 2)
void gemm_qkv(const __nv_bfloat16* __restrict__ qh, const __nv_bfloat16* __restrict__ ql,
              const __nv_bfloat16* __restrict__ wqh, const __nv_bfloat16* __restrict__ wql,
              __nv_bfloat16* __restrict__ PQh, __nv_bfloat16* __restrict__ PQl,
              const __nv_bfloat16* __restrict__ kvh, const __nv_bfloat16* __restrict__ kvl,
              const __nv_bfloat16* __restrict__ wkh, const __nv_bfloat16* __restrict__ wkl,
              __nv_bfloat16* __restrict__ PKh, __nv_bfloat16* __restrict__ PKl)
{
    extern __shared__ char sm[];
    int bx = blockIdx.x;
    if (bx < 768) {
        int nb = bx % 12, mb = bx / 12;
        gemm_body(qh, ql, wqh, wql, nullptr, nullptr, PQh, PQl,
                  DIMC, DIMC, mb * 128, nb * 64, sm);
    } else {
        int t = bx - 768;
        int nb = t % 24, mb = t / 24;
        gemm_body(kvh, kvl, wkh, wkl, nullptr, nullptr, PKh, PKl,
                  2 * DIMC, DIMC, mb * 128, nb * 64, sm);
    }
}

__global__ __launch_bounds__(256, 2)
void gemm_proj(const __nv_bfloat16* __restrict__ oh, const __nv_bfloat16* __restrict__ ol,
               const __nv_bfloat16* __restrict__ wph, const __nv_bfloat16* __restrict__ wpl,
               const float* __restrict__ bias, float* __restrict__ out)
{
    extern __shared__ char sm[];
    int nb = blockIdx.x % 12, mb = blockIdx.x / 12;
    gemm_body(oh, ol, wph, wpl, bias, out, nullptr, nullptr,
              DIMC, DIMC, mb * 128, nb * 64, sm);
}

// ---------------------------------------------------------------------------
// One merged fp32 -> (hi,lo) bf16 split over all 5 input arrays.
// ---------------------------------------------------------------------------
#define N4_Q   ((size_t)MROWS * DIMC / 4)
#define N4_W1  ((size_t)DIMC * DIMC / 4)
#define N4_W2  ((size_t)2 * DIMC * DIMC / 4)
#define N4_TOT (N4_Q + N4_Q + N4_W1 + N4_W2 + N4_W1)

__global__ __launch_bounds__(256)
void cvt_all(const float4* __restrict__ q,   uint2* __restrict__ qh,  uint2* __restrict__ ql,
             const float4* __restrict__ kv,  uint2* __restrict__ kvh, uint2* __restrict__ kvl,
             const float4* __restrict__ wq,  uint2* __restrict__ wqh, uint2* __restrict__ wql,
             const float4* __restrict__ wkv, uint2* __restrict__ wkh, uint2* __restrict__ wkl,
             const float4* __restrict__ wp,  uint2* __restrict__ wph, uint2* __restrict__ wpl)
{
    size_t i = (size_t)blockIdx.x * blockDim.x + threadIdx.x;
    if (i >= N4_TOT) return;
    const float4* src; uint2 *hi, *lo; size_t j = i;
    if (j < N4_Q)                 { src = q;   hi = qh;  lo = ql;  }
    else if ((j -= N4_Q) < N4_Q)  { src = kv;  hi = kvh; lo = kvl; }
    else if ((j -= N4_Q) < N4_W1) { src = wq;  hi = wqh; lo = wql; }
    else if ((j -= N4_W1) < N4_W2){ src = wkv; hi = wkh; lo = wkl; }
    else { j -= N4_W2;              src = wp;  hi = wph; lo = wpl; }

    float4 x = src[j];
    __nv_bfloat162 h01 = __floats2bfloat162_rn(x.x, x.y);
    __nv_bfloat162 h23 = __floats2bfloat162_rn(x.z, x.w);
    float r0 = x.x - __low2float(h01), r1 = x.y - __high2float(h01);
    float r2 = x.z - __low2float(h23), r3 = x.w - __high2float(h23);
    __nv_bfloat162 l01 = __floats2bfloat162_rn(r0, r1);
    __nv_bfloat162 l23 = __floats2bfloat162_rn(r2, r3);
    hi[j] = make_uint2(*(uint32_t*)&h01, *(uint32_t*)&h23);
    lo[j] = make_uint2(*(uint32_t*)&l01, *(uint32_t*)&l23);
}

// ---------------------------------------------------------------------------
// Tensor-core flash attention, bf16-split. kv-tile 64, pos via direct LDG
// into accumulators, 2 CTAs/SM.
// smem: Qh|Ql (32KB) + 2 stages { KH,KL,VH,VL 8KB each } = 96KB
// ---------------------------------------------------------------------------
#define AQ_H     0
#define AQ_L     16384
#define AST_BASE 32768
#define AST_KH   0
#define AST_KL   8192
#define AST_VH   16384
#define AST_VL   24576
#define AST_SIZE 32768
#define ATTN_SMEM (AST_BASE + 2 * AST_SIZE)   // 98304

__global__ __launch_bounds__(256, 2)
void attn_mma(const __nv_bfloat16* __restrict__ Qh, const __nv_bfloat16* __restrict__ Ql,
              const __nv_bfloat16* __restrict__ KVh, const __nv_bfloat16* __restrict__ KVl,
              const float* __restrict__ pos,
              __nv_bfloat16* __restrict__ Oh, __nv_bfloat16* __restrict__ Ol)
{
    extern __shared__ char sm[];
    const uint32_t smb = smem_u32(sm);
    const int tid = threadIdx.x, wid = tid >> 5, lane = tid & 31;
    const int b = blockIdx.z, h = blockIdx.y;
    const int q0 = blockIdx.x * 128;

    const int g = lane >> 3, r = lane & 7;
    const int arl = (g & 1) * 8 + r, acs = g >> 1;
    const int brl = (g >> 1) * 8 + r, bcs = g & 1;
    const int er = lane >> 2, ec = (lane & 3) * 2;

    // stage Q tile (hi/lo) once
    const size_t qrow0 = (size_t)(b * LQ + q0);
    for (int i = tid; i < 128 * 8; i += 256) {
        int row = i >> 3, c16 = i & 7;
        size_t off = (qrow0 + row) * DIMC + h * HDIM + c16 * 8;
        uint32_t d = swz(row, c16);
        cp16(smb + AQ_H + d, Qh + off);
        cp16(smb + AQ_L + d, Ql + off);
    }
    CP_COMMIT();

    // per-thread pos base: rows (wid*16+er, +8), cols ec + nt*8
    const float* pb0 = pos + ((size_t)(h * LQ + q0 + wid * 16 + er)) * LKV + ec;
    const float* pb1 = pb0 + (size_t)8 * LKV;

    auto stage = [&](int c) {
        const uint32_t sb = smb + AST_BASE + (uint32_t)(c & 1) * AST_SIZE;
        const int kv0 = c * 64;
        const size_t kvrow0 = (size_t)(b * LKV + kv0);
#pragma unroll
        for (int jj = 0; jj < 2; jj++) {
            int i = tid + jj * 256;
            int row = i >> 3, c16 = i & 7;
            size_t off = (kvrow0 + row) * KVSTR + h * HDIM + c16 * 8;
            uint32_t d = swz(row, c16);
            cp16(sb + AST_KH + d, KVh + off);
            cp16(sb + AST_KL + d, KVl + off);
            cp16(sb + AST_VH + d, KVh + off + DIMC);
            cp16(sb + AST_VL + d, KVl + off + DIMC);
        }
        CP_COMMIT();
    };

    float O[8][4];
#pragma unroll
    for (int nt = 0; nt < 8; nt++)
#pragma unroll
        for (int j = 0; j < 4; j++) O[nt][j] = 0.f;
    float mv0 = -1e30f, mv1 = -1e30f, l0 = 0.f, l1 = 0.f;

    stage(0);

    const int NT = LKV / 64;   // 16
    for (int c = 0; c < NT; ++c) {
        __syncthreads();
        if (c + 1 < NT) {
            stage(c + 1);
            asm volatile("cp.async.wait_group 1;" ::: "memory");
        } else {
            asm volatile("cp.async.wait_group 0;" ::: "memory");
        }
        __syncthreads();

        const uint32_t sb = smb + AST_BASE + (uint32_t)(c & 1) * AST_SIZE;

        // init S accumulator with 8*pos via direct LDG (other CTA hides latency)
        float acc[8][4];
        {
            const int off = c * 64;
#pragma unroll
            for (int nt = 0; nt < 8; nt++) {
                float2 p0 = *(const float2*)(pb0 + off + nt * 8);
                float2 p1 = *(const float2*)(pb1 + off + nt * 8);
                acc[nt][0] = 8.f * p0.x; acc[nt][1] = 8.f * p0.y;
                acc[nt][2] = 8.f * p1.x; acc[nt][3] = 8.f * p1.y;
            }
        }

        // S = Q K^T (3-pass split); K frags 2 blocks at a time,
        // mma round-robin over 4 accumulators (RAW distance 4)
        {
            const uint32_t qbh = smb + AQ_H, qbl = smb + AQ_L;
            const uint32_t kbh = sb + AST_KH, kbl = sb + AST_KL;
#pragma unroll
            for (int ks = 0; ks < 4; ks++) {
                uint32_t qf_h[4], qf_l[4];
                ldsm4(qf_h, qbh + swz(wid * 16 + arl, ks * 2 + acs));
                ldsm4(qf_l, qbl + swz(wid * 16 + arl, ks * 2 + acs));
#pragma unroll
                for (int pp = 0; pp < 2; pp++) {      // pp covers p = 2*pp, 2*pp+1
                    uint32_t kh[2][4], kl[2][4];
#pragma unroll
                    for (int u = 0; u < 2; u++) {
                        ldsm4(kh[u], kbh + swz((pp * 2 + u) * 16 + brl, ks * 2 + bcs));
                        ldsm4(kl[u], kbl + swz((pp * 2 + u) * 16 + brl, ks * 2 + bcs));
                    }
                    float* a0 = acc[pp * 4 + 0]; float* a1 = acc[pp * 4 + 1];
                    float* a2 = acc[pp * 4 + 2]; float* a3 = acc[pp * 4 + 3];
                    mma16816(a0, qf_h, &kh[0][0]);
                    mma16816(a1, qf_h, &kh[0][2]);
                    mma16816(a2, qf_h, &kh[1][0]);
                    mma16816(a3, qf_h, &kh[1][2]);
                    mma16816(a0, qf_h, &kl[0][0]);
                    mma16816(a1, qf_h, &kl[0][2]);
                    mma16816(a2, qf_h, &kl[1][0]);
                    mma16816(a3, qf_h, &kl[1][2]);
                    mma16816(a0, qf_l, &kh[0][0]);
                    mma16816(a1, qf_l, &kh[0][2]);
                    mma16816(a2, qf_l, &kh[1][0]);
                    mma16816(a3, qf_l, &kh[1][2]);
                }
            }
        }

        // online softmax on fragments
        float tmax0 = mv0, tmax1 = mv1;
#pragma unroll
        for (int nt = 0; nt < 8; nt++) {
            acc[nt][0] *= SCALE; acc[nt][1] *= SCALE;
            acc[nt][2] *= SCALE; acc[nt][3] *= SCALE;
            tmax0 = fmaxf(tmax0, fmaxf(acc[nt][0], acc[nt][1]));
            tmax1 = fmaxf(tmax1, fmaxf(acc[nt][2], acc[nt][3]));
        }
        tmax0 = fmaxf(tmax0, __shfl_xor_sync(0xffffffffu, tmax0, 1));
        tmax0 = fmaxf(tmax0, __shfl_xor_sync(0xffffffffu, tmax0, 2));
        tmax1 = fmaxf(tmax1, __shfl_xor_sync(0xffffffffu, tmax1, 1));
        tmax1 = fmaxf(tmax1, __shfl_xor_sync(0xffffffffu, tmax1, 2));

        float alpha0 = __expf(mv0 - tmax0);
        float alpha1 = __expf(mv1 - tmax1);
        mv0 = tmax0; mv1 = tmax1;

        uint32_t pa_h[4][4], pa_l[4][4];
        float la0 = 0.f, la1 = 0.f;
#pragma unroll
        for (int nt = 0; nt < 8; nt++) {
            float p0 = __expf(acc[nt][0] - mv0);
            float p1 = __expf(acc[nt][1] - mv0);
            float p2 = __expf(acc[nt][2] - mv1);
            float p3 = __expf(acc[nt][3] - mv1);
            la0 += p0 + p1; la1 += p2 + p3;
            __nv_bfloat162 h01 = __floats2bfloat162_rn(p0, p1);
            __nv_bfloat162 h23 = __floats2bfloat162_rn(p2, p3);
            float q0f = p0 - __low2float(h01), q1f = p1 - __high2float(h01);
            float q2f = p2 - __low2float(h23), q3f = p3 - __high2float(h23);
            int t = nt >> 1, base = (nt & 1) * 2;
            pa_h[t][base + 0] = *(uint32_t*)&h01;
            pa_h[t][base + 1] = *(uint32_t*)&h23;
            pa_l[t][base + 0] = packbf(q0f, q1f);
            pa_l[t][base + 1] = packbf(q2f, q3f);
        }
        l0 = l0 * alpha0 + la0;
        l1 = l1 * alpha1 + la1;

#pragma unroll
        for (int nt = 0; nt < 8; nt++) {
            O[nt][0] *= alpha0; O[nt][1] *= alpha0;
            O[nt][2] *= alpha1; O[nt][3] *= alpha1;
        }

        // O += P V (3-pass split); V frags 2 blocks at a time,
        // mma round-robin over 4 O accumulators
        {
            const uint32_t vbh = sb + AST_VH, vbl = sb + AST_VL;
#pragma unroll
            for (int ks = 0; ks < 4; ks++) {
#pragma unroll
                for (int tq = 0; tq < 2; tq++) {      // tq covers tp = 2*tq, 2*tq+1
                    uint32_t vh[2][4], vl[2][4];
#pragma unroll
                    for (int u = 0; u < 2; u++) {
                        ldsm4t(vh[u], vbh + swz(ks * 16 + arl, (tq * 2 + u) * 2 + acs));
                        ldsm4t(vl[u], vbl + swz(ks * 16 + arl, (tq * 2 + u) * 2 + acs));
                    }
                    float* o0 = O[tq * 4 + 0]; float* o1 = O[tq * 4 + 1];
                    float* o2 = O[tq * 4 + 2]; float* o3 = O[tq * 4 + 3];
                    mma16816(o0, pa_h[ks], &vh[0][0]);
                    mma16816(o1, pa_h[ks], &vh[0][2]);
                    mma16816(o2, pa_h[ks], &vh[1][0]);
                    mma16816(o3, pa_h[ks], &vh[1][2]);
                    mma16816(o0, pa_h[ks], &vl[0][0]);
                    mma16816(o1, pa_h[ks], &vl[0][2]);
                    mma16816(o2, pa_h[ks], &vl[1][0]);
                    mma16816(o3, pa_h[ks], &vl[1][2]);
                    mma16816(o0, pa_l[ks], &vh[0][0]);
                    mma16816(o1, pa_l[ks], &vh[0][2]);
                    mma16816(o2, pa_l[ks], &vh[1][0]);
                    mma16816(o3, pa_l[ks], &vh[1][2]);
                }
            }
        }
    }

    l0 += __shfl_xor_sync(0xffffffffu, l0, 1);
    l0 += __shfl_xor_sync(0xffffffffu, l0, 2);
    l1 += __shfl_xor_sync(0xffffffffu, l1, 1);
    l1 += __shfl_xor_sync(0xffffffffu, l1, 2);
    float inv0 = 1.f / l0, inv1 = 1.f / l1;

    const size_t row0 = (size_t)(b * LQ + q0 + wid * 16 + er);
#pragma unroll
    for (int nt = 0; nt < 8; nt++) {
        int col = h * HDIM + nt * 8 + ec;
        float v0 = O[nt][0] * inv0, v1 = O[nt][1] * inv0;
        float v2 = O[nt][2] * inv1, v3 = O[nt][3] * inv1;
        __nv_bfloat162 h01 = __floats2bfloat162_rn(v0, v1);
        __nv_bfloat162 h23 = __floats2bfloat162_rn(v2, v3);
        float q0f = v0 - __low2float(h01), q1f = v1 - __high2float(h01);
        float q2f = v2 - __low2float(h23), q3f = v3 - __high2float(h23);
        size_t offA = row0 * DIMC + col;
        size_t offB = (row0 + 8) * DIMC + col;
        *(uint32_t*)(Oh + offA) = *(uint32_t*)&h01;
        *(uint32_t*)(Ol + offA) = packbf(q0f, q1f);
        *(uint32_t*)(Oh + offB) = *(uint32_t*)&h23;
        *(uint32_t*)(Ol + offB) = packbf(q2f, q3f);
    }
}

// ---------------------------------------------------------------------------
extern "C" void kernel_launch(void* const* d_in, const int* in_sizes, int n_in,
                              void* d_out, int out_size)
{
    (void)in_sizes; (void)n_in; (void)out_size;
    const float* q     = (const float*)d_in[0];
    const float* kv    = (const float*)d_in[1];
    const float* pos   = (const float*)d_in[2];
    const float* Wq    = (const float*)d_in[3];
    const float* Wkv   = (const float*)d_in[4];
    const float* Wproj = (const float*)d_in[5];
    const float* bproj = (const float*)d_in[6];
    float* out = (float*)d_out;

    __nv_bfloat16 *qh, *ql, *kvh, *kvl, *wqh, *wql, *wkh, *wkl, *wph, *wpl;
    __nv_bfloat16 *PQh, *PQl, *PKh, *PKl, *oh, *ol;
    cudaGetSymbolAddress((void**)&qh,  g_qh);   cudaGetSymbolAddress((void**)&ql,  g_ql);
    cudaGetSymbolAddress((void**)&kvh, g_kvh);  cudaGetSymbolAddress((void**)&kvl, g_kvl);
    cudaGetSymbolAddress((void**)&wqh, g_wqh);  cudaGetSymbolAddress((void**)&wql, g_wql);
    cudaGetSymbolAddress((void**)&wkh, g_wkh);  cudaGetSymbolAddress((void**)&wkl, g_wkl);
    cudaGetSymbolAddress((void**)&wph, g_wph);  cudaGetSymbolAddress((void**)&wpl, g_wpl);
    cudaGetSymbolAddress((void**)&PQh, g_PQh);  cudaGetSymbolAddress((void**)&PQl, g_PQl);
    cudaGetSymbolAddress((void**)&PKh, g_PKh);  cudaGetSymbolAddress((void**)&PKl, g_PKl);
    cudaGetSymbolAddress((void**)&oh,  g_oh);   cudaGetSymbolAddress((void**)&ol,  g_ol);

    static bool attr_done = false;
    if (!attr_done) {
        cudaFuncSetAttribute(gemm_qkv,  cudaFuncAttributeMaxDynamicSharedMemorySize, GEMM_SMEM);
        cudaFuncSetAttribute(gemm_proj, cudaFuncAttributeMaxDynamicSharedMemorySize, GEMM_SMEM);
        cudaFuncSetAttribute(attn_mma,  cudaFuncAttributeMaxDynamicSharedMemorySize, ATTN_SMEM);
        attr_done = true;
    }

    {
        int grid = (int)((N4_TOT + 255) / 256);
        cvt_all<<<grid, 256>>>(
            (const float4*)q,   (uint2*)qh,  (uint2*)ql,
            (const float4*)kv,  (uint2*)kvh, (uint2*)kvl,
            (const float4*)Wq,  (uint2*)wqh, (uint2*)wql,
            (const float4*)Wkv, (uint2*)wkh, (uint2*)wkl,
            (const float4*)Wproj, (uint2*)wph, (uint2*)wpl);
    }

    gemm_qkv<<<2304, 256, GEMM_SMEM>>>(qh, ql, wqh, wql, PQh, PQl,
                                       kvh, kvl, wkh, wkl, PKh, PKl);

    attn_mma<<<dim3(LQ / 128, NHEADS, BATCH), 256, ATTN_SMEM>>>(
        PQh, PQl, PKh, PKl, pos, oh, ol);

    gemm_proj<<<768, 256, GEMM_SMEM>>>(oh, ol, wph, wpl, bproj, out);
}

// round 13
// speedup vs baseline: 1.4152x; 1.3347x over previous
#include <cuda_runtime.h>
#include <cuda_fp16.h>
#include <cstdint>
#include <cstddef>

// Problem constants
#define DIMC   768
#define NHEADS 12
#define HDIM   64
#define BATCH  8
#define LQ     1024
#define LKV    1024
#define SCALE  0.125f
#define KVSTR  (2 * DIMC)       // 1536 (elements)

#define MROWS  (BATCH * LQ)     // 8192

// fp16 split scratch (hi/lo for activations; weights use hi only)
__device__ __half g_qh  [(size_t)MROWS * DIMC];
__device__ __half g_ql  [(size_t)MROWS * DIMC];
__device__ __half g_kvh [(size_t)MROWS * DIMC];
__device__ __half g_kvl [(size_t)MROWS * DIMC];
__device__ __half g_wqh [(size_t)DIMC * DIMC];
__device__ __half g_wql [(size_t)DIMC * DIMC];
__device__ __half g_wkh [(size_t)2 * DIMC * DIMC];
__device__ __half g_wkl [(size_t)2 * DIMC * DIMC];
__device__ __half g_wph [(size_t)DIMC * DIMC];
__device__ __half g_wpl [(size_t)DIMC * DIMC];
__device__ __half g_PQh [(size_t)MROWS * DIMC];
__device__ __half g_PQl [(size_t)MROWS * DIMC];
__device__ __half g_PKh [(size_t)MROWS * 2 * DIMC];   // K|V hi only
__device__ __half g_oh  [(size_t)MROWS * DIMC];
__device__ __half g_ol  [(size_t)MROWS * DIMC];

// ---------------------------------------------------------------------------
__device__ __forceinline__ uint32_t smem_u32(const void* p) {
    uint32_t a;
    asm("{ .reg .u64 t; cvta.to.shared.u64 t, %1; cvt.u32.u64 %0, t; }" : "=r"(a) : "l"(p));
    return a;
}
__device__ __forceinline__ void ldsm4(uint32_t* r, uint32_t addr) {
    asm volatile("ldmatrix.sync.aligned.m8n8.x4.shared.b16 {%0,%1,%2,%3}, [%4];"
        : "=r"(r[0]), "=r"(r[1]), "=r"(r[2]), "=r"(r[3]) : "r"(addr));
}
__device__ __forceinline__ void ldsm4t(uint32_t* r, uint32_t addr) {
    asm volatile("ldmatrix.sync.aligned.m8n8.x4.trans.shared.b16 {%0,%1,%2,%3}, [%4];"
        : "=r"(r[0]), "=r"(r[1]), "=r"(r[2]), "=r"(r[3]) : "r"(addr));
}
// fp16 mma with fp32 accumulate
__device__ __forceinline__ void mma16816(float* d, const uint32_t* a, const uint32_t* b) {
    asm volatile("mma.sync.aligned.m16n8k16.row.col.f32.f16.f16.f32 "
        "{%0,%1,%2,%3}, {%4,%5,%6,%7}, {%8,%9}, {%0,%1,%2,%3};"
        : "+f"(d[0]), "+f"(d[1]), "+f"(d[2]), "+f"(d[3])
        : "r"(a[0]), "r"(a[1]), "r"(a[2]), "r"(a[3]), "r"(b[0]), "r"(b[1]));
}
__device__ __forceinline__ void cp16(uint32_t dst, const void* src) {
    asm volatile("cp.async.cg.shared.global [%0], [%1], 16;" :: "r"(dst), "l"(src) : "memory");
}
#define CP_COMMIT() asm volatile("cp.async.commit_group;" ::: "memory")

__device__ __forceinline__ uint32_t packh(float a, float b) {
    __half2 t = __floats2half2_rn(a, b);
    return *(uint32_t*)&t;
}

// swizzled byte offset inside a 128B-row tile
__device__ __forceinline__ uint32_t swz(int row, int c16) {
    return (uint32_t)(row * 128 + ((c16 ^ (row & 7)) << 4));
}

// ---------------------------------------------------------------------------
// GEMM: tile 128(M)x64(N), 256 threads, warp 32x32 (4x2 grid), K-chunks 64,
// 2-stage cp.async, 2 CTAs/SM. fp16 2-pass: C = Ah*W + Al*W.
// ---------------------------------------------------------------------------
#define GSTG   40960          // AH 16K | AL 16K | W 8K
#define GB_AH  0
#define GB_AL  16384
#define GB_W   32768
#define GEMM_SMEM (2 * GSTG)  // 81920

__device__ __forceinline__ void stageA(uint32_t sdst, const __half* rowbase,
                                       int K, int k0, int tid) {
#pragma unroll
    for (int rep = 0; rep < 4; rep++) {
        int i = tid + rep * 256;
        int row = i >> 3, c16 = i & 7;
        cp16(sdst + swz(row, c16), rowbase + (size_t)row * K + k0 + c16 * 8);
    }
}
__device__ __forceinline__ void stageW(uint32_t sdst, const __half* rowbase,
                                       int K, int k0, int tid) {
#pragma unroll
    for (int rep = 0; rep < 2; rep++) {
        int i = tid + rep * 256;
        int row = i >> 3, c16 = i & 7;
        cp16(sdst + swz(row, c16), rowbase + (size_t)row * K + k0 + c16 * 8);
    }
}

__device__ __forceinline__
void gemm_body(const __half* __restrict__ Ah, const __half* __restrict__ Al,
               const __half* __restrict__ W,
               const float* __restrict__ bias, float* __restrict__ C,
               __half* __restrict__ Ch, __half* __restrict__ Cl,
               int N, int K, int m0, int n0, char* sm)
{
    const uint32_t smb = smem_u32(sm);
    const int tid = threadIdx.x;
    const int wid = tid >> 5, lane = tid & 31;
    const int wm = wid >> 1, wn = wid & 1;

    const __half* Ahb = Ah + (size_t)m0 * K;
    const __half* Alb = Al + (size_t)m0 * K;
    const __half* Wb  = W  + (size_t)n0 * K;

    const int g = lane >> 3, r = lane & 7;
    const int arl = (g & 1) * 8 + r;
    const int acs = g >> 1;
    const int brl = (g >> 1) * 8 + r;
    const int bcs = g & 1;

    float acc[2][4][4];
#pragma unroll
    for (int i = 0; i < 2; i++)
#pragma unroll
        for (int j = 0; j < 4; j++)
#pragma unroll
            for (int k = 0; k < 4; k++) acc[i][j][k] = 0.f;

    const int NC = K >> 6;   // 12

    {
        uint32_t sb = smb;
        stageA(sb + GB_AH, Ahb, K, 0, tid);
        stageA(sb + GB_AL, Alb, K, 0, tid);
        stageW(sb + GB_W,  Wb,  K, 0, tid);
        CP_COMMIT();
    }

    for (int c = 0; c < NC; ++c) {
        if (c + 1 < NC) {
            uint32_t sb = smb + ((c + 1) & 1) * GSTG;
            int k0 = (c + 1) << 6;
            stageA(sb + GB_AH, Ahb, K, k0, tid);
            stageA(sb + GB_AL, Alb, K, k0, tid);
            stageW(sb + GB_W,  Wb,  K, k0, tid);
            CP_COMMIT();
            asm volatile("cp.async.wait_group 1;" ::: "memory");
        } else {
            asm volatile("cp.async.wait_group 0;" ::: "memory");
        }
        __syncthreads();

        const uint32_t sb = smb + (c & 1) * GSTG;
        const uint32_t bAh = sb + GB_AH, bAl = sb + GB_AL, bW = sb + GB_W;

#pragma unroll
        for (int s = 0; s < 4; ++s) {
            uint32_t ah[2][4], al[2][4], bw[2][4];
#pragma unroll
            for (int mt = 0; mt < 2; ++mt) {
                ldsm4(ah[mt], bAh + swz(wm * 32 + mt * 16 + arl, s * 2 + acs));
                ldsm4(al[mt], bAl + swz(wm * 32 + mt * 16 + arl, s * 2 + acs));
            }
#pragma unroll
            for (int p = 0; p < 2; ++p)
                ldsm4(bw[p], bW + swz(wn * 32 + p * 16 + brl, s * 2 + bcs));

#pragma unroll
            for (int mt = 0; mt < 2; ++mt)
#pragma unroll
                for (int nt = 0; nt < 4; ++nt)
                    mma16816(acc[mt][nt], ah[mt], &bw[nt >> 1][(nt & 1) * 2]);
#pragma unroll
            for (int mt = 0; mt < 2; ++mt)
#pragma unroll
                for (int nt = 0; nt < 4; ++nt)
                    mma16816(acc[mt][nt], al[mt], &bw[nt >> 1][(nt & 1) * 2]);
        }
        __syncthreads();
    }

    const int er = lane >> 2, ec = (lane & 3) * 2;
    if (Ch) {
#pragma unroll
        for (int mt = 0; mt < 2; ++mt) {
#pragma unroll
            for (int nt = 0; nt < 4; ++nt) {
                int grow = m0 + wm * 32 + mt * 16 + er;
                int gcol = n0 + wn * 32 + nt * 8 + ec;
#pragma unroll
                for (int rr = 0; rr < 2; ++rr) {
                    float v0 = acc[mt][nt][rr * 2 + 0];
                    float v1 = acc[mt][nt][rr * 2 + 1];
                    __half2 hp = __floats2half2_rn(v0, v1);
                    size_t off = (size_t)(grow + rr * 8) * N + gcol;
                    *(uint32_t*)(Ch + off) = *(uint32_t*)&hp;
                    if (Cl) {
                        float2 hf = __half22float2(hp);
                        *(uint32_t*)(Cl + off) = packh(v0 - hf.x, v1 - hf.y);
                    }
                }
            }
        }
    } else {
#pragma unroll
        for (int mt = 0; mt < 2; ++mt) {
#pragma unroll
            for (int nt = 0; nt < 4; ++nt) {
                int grow = m0 + wm * 32 + mt * 16 + er;
                int gcol = n0 + wn * 32 + nt * 8 + ec;
                float b0 = 0.f, b1 = 0.f;
                if (bias) { b0 = bias[gcol]; b1 = bias[gcol + 1]; }
                float2 v0 = make_float2(acc[mt][nt][0] + b0, acc[mt][nt][1] + b1);
                float2 v1 = make_float2(acc[mt][nt][2] + b0, acc[mt][nt][3] + b1);
                *(float2*)(C + (size_t)grow * N + gcol) = v0;
                *(float2*)(C + (size_t)(grow + 8) * N + gcol) = v1;
            }
        }
    }
}

// Combined Q + KV projection gemm. Q tiles write hi+lo; KV tiles hi only.
__global__ __launch_bounds__(256, 2)
void gemm_qkv(const __half* __restrict__ qh, const __half* __restrict__ ql,
              const __half* __restrict__ wqh,
              __half* __restrict__ PQh, __half* __restrict__ PQl,
              const __half* __restrict__ kvh, const __half* __restrict__ kvl,
              const __half* __restrict__ wkh,
              __half* __restrict__ PKh)
{
    extern __shared__ char sm[];
    int bx = blockIdx.x;
    if (bx < 768) {
        int nb = bx % 12, mb = bx / 12;
        gemm_body(qh, ql, wqh, nullptr, nullptr, PQh, PQl,
                  DIMC, DIMC, mb * 128, nb * 64, sm);
    } else {
        int t = bx - 768;
        int nb = t % 24, mb = t / 24;
        gemm_body(kvh, kvl, wkh, nullptr, nullptr, PKh, nullptr,
                  2 * DIMC, DIMC, mb * 128, nb * 64, sm);
    }
}

// Output projection gemm (fp32 out + bias).
__global__ __launch_bounds__(256, 2)
void gemm_proj(const __half* __restrict__ oh, const __half* __restrict__ ol,
               const __half* __restrict__ wph,
               const float* __restrict__ bias, float* __restrict__ out)
{
    extern __shared__ char sm[];
    int nb = blockIdx.x % 12, mb = blockIdx.x / 12;
    gemm_body(oh, ol, wph, bias, out, nullptr, nullptr,
              DIMC, DIMC, mb * 128, nb * 64, sm);
}

// ---------------------------------------------------------------------------
// One merged fp32 -> (hi,lo) fp16 split over all 5 input arrays.
// ---------------------------------------------------------------------------
#define N4_Q   ((size_t)MROWS * DIMC / 4)
#define N4_W1  ((size_t)DIMC * DIMC / 4)
#define N4_W2  ((size_t)2 * DIMC * DIMC / 4)
#define N4_TOT (N4_Q + N4_Q + N4_W1 + N4_W2 + N4_W1)

__global__ __launch_bounds__(256)
void cvt_all(const float4* __restrict__ q,   uint2* __restrict__ qh,  uint2* __restrict__ ql,
             const float4* __restrict__ kv,  uint2* __restrict__ kvh, uint2* __restrict__ kvl,
             const float4* __restrict__ wq,  uint2* __restrict__ wqh, uint2* __restrict__ wql,
             const float4* __restrict__ wkv, uint2* __restrict__ wkh, uint2* __restrict__ wkl,
             const float4* __restrict__ wp,  uint2* __restrict__ wph, uint2* __restrict__ wpl)
{
    size_t i = (size_t)blockIdx.x * blockDim.x + threadIdx.x;
    if (i >= N4_TOT) return;
    const float4* src; uint2 *hi, *lo; size_t j = i;
    if (j < N4_Q)                 { src = q;   hi = qh;  lo = ql;  }
    else if ((j -= N4_Q) < N4_Q)  { src = kv;  hi = kvh; lo = kvl; }
    else if ((j -= N4_Q) < N4_W1) { src = wq;  hi = wqh; lo = wql; }
    else if ((j -= N4_W1) < N4_W2){ src = wkv; hi = wkh; lo = wkl; }
    else { j -= N4_W2;              src = wp;  hi = wph; lo = wpl; }

    float4 x = src[j];
    __half2 h01 = __floats2half2_rn(x.x, x.y);
    __half2 h23 = __floats2half2_rn(x.z, x.w);
    float2 f01 = __half22float2(h01), f23 = __half22float2(h23);
    __half2 l01 = __floats2half2_rn(x.x - f01.x, x.y - f01.y);
    __half2 l23 = __floats2half2_rn(x.z - f23.x, x.w - f23.y);
    hi[j] = make_uint2(*(uint32_t*)&h01, *(uint32_t*)&h23);
    lo[j] = make_uint2(*(uint32_t*)&l01, *(uint32_t*)&l23);
}

// ---------------------------------------------------------------------------
// Tensor-core flash attention, fp16 2-pass. kv-tile 64, pos via direct LDG,
// 2 CTAs/SM. smem: Qh|Ql (32KB) + 2 stages { KH 8K, VH 8K } = 64KB
// ---------------------------------------------------------------------------
#define AQ_H     0
#define AQ_L     16384
#define AST_BASE 32768
#define AST_KH   0
#define AST_VH   8192
#define AST_SIZE 16384
#define ATTN_SMEM (AST_BASE + 2 * AST_SIZE)   // 65536

__global__ __launch_bounds__(256, 2)
void attn_mma(const __half* __restrict__ Qh, const __half* __restrict__ Ql,
              const __half* __restrict__ KVh,
              const float* __restrict__ pos,
              __half* __restrict__ Oh, __half* __restrict__ Ol)
{
    extern __shared__ char sm[];
    const uint32_t smb = smem_u32(sm);
    const int tid = threadIdx.x, wid = tid >> 5, lane = tid & 31;
    const int b = blockIdx.z, h = blockIdx.y;
    const int q0 = blockIdx.x * 128;

    const int g = lane >> 3, r = lane & 7;
    const int arl = (g & 1) * 8 + r, acs = g >> 1;
    const int brl = (g >> 1) * 8 + r, bcs = g & 1;
    const int er = lane >> 2, ec = (lane & 3) * 2;

    // stage Q tile (hi/lo) once
    const size_t qrow0 = (size_t)(b * LQ + q0);
    for (int i = tid; i < 128 * 8; i += 256) {
        int row = i >> 3, c16 = i & 7;
        size_t off = (qrow0 + row) * DIMC + h * HDIM + c16 * 8;
        uint32_t d = swz(row, c16);
        cp16(smb + AQ_H + d, Qh + off);
        cp16(smb + AQ_L + d, Ql + off);
    }
    CP_COMMIT();

    // per-thread pos base: rows (wid*16+er, +8), cols ec + nt*8
    const float* pb0 = pos + ((size_t)(h * LQ + q0 + wid * 16 + er)) * LKV + ec;
    const float* pb1 = pb0 + (size_t)8 * LKV;

    auto stage = [&](int c) {
        const uint32_t sb = smb + AST_BASE + (uint32_t)(c & 1) * AST_SIZE;
        const int kv0 = c * 64;
        const size_t kvrow0 = (size_t)(b * LKV + kv0);
#pragma unroll
        for (int jj = 0; jj < 2; jj++) {
            int i = tid + jj * 256;
            int row = i >> 3, c16 = i & 7;
            size_t off = (kvrow0 + row) * KVSTR + h * HDIM + c16 * 8;
            uint32_t d = swz(row, c16);
            cp16(sb + AST_KH + d, KVh + off);
            cp16(sb + AST_VH + d, KVh + off + DIMC);
        }
        CP_COMMIT();
    };

    float O[8][4];
#pragma unroll
    for (int nt = 0; nt < 8; nt++)
#pragma unroll
        for (int j = 0; j < 4; j++) O[nt][j] = 0.f;
    float mv0 = -1e30f, mv1 = -1e30f, l0 = 0.f, l1 = 0.f;

    stage(0);

    const int NT = LKV / 64;   // 16
    for (int c = 0; c < NT; ++c) {
        __syncthreads();
        if (c + 1 < NT) {
            stage(c + 1);
            asm volatile("cp.async.wait_group 1;" ::: "memory");
        } else {
            asm volatile("cp.async.wait_group 0;" ::: "memory");
        }
        __syncthreads();

        const uint32_t sb = smb + AST_BASE + (uint32_t)(c & 1) * AST_SIZE;

        // init S accumulator with 8*pos via direct LDG
        float acc[8][4];
        {
            const int off = c * 64;
#pragma unroll
            for (int nt = 0; nt < 8; nt++) {
                float2 p0 = *(const float2*)(pb0 + off + nt * 8);
                float2 p1 = *(const float2*)(pb1 + off + nt * 8);
                acc[nt][0] = 8.f * p0.x; acc[nt][1] = 8.f * p0.y;
                acc[nt][2] = 8.f * p1.x; acc[nt][3] = 8.f * p1.y;
            }
        }

        // S = Q K^T (2-pass: Qh*K + Ql*K)
        {
            const uint32_t qbh = smb + AQ_H, qbl = smb + AQ_L;
            const uint32_t kbh = sb + AST_KH;
#pragma unroll
            for (int ks = 0; ks < 4; ks++) {
                uint32_t qf_h[4], qf_l[4];
                ldsm4(qf_h, qbh + swz(wid * 16 + arl, ks * 2 + acs));
                ldsm4(qf_l, qbl + swz(wid * 16 + arl, ks * 2 + acs));
#pragma unroll
                for (int pp = 0; pp < 2; pp++) {
                    uint32_t kh[2][4];
#pragma unroll
                    for (int u = 0; u < 2; u++)
                        ldsm4(kh[u], kbh + swz((pp * 2 + u) * 16 + brl, ks * 2 + bcs));
                    float* a0 = acc[pp * 4 + 0]; float* a1 = acc[pp * 4 + 1];
                    float* a2 = acc[pp * 4 + 2]; float* a3 = acc[pp * 4 + 3];
                    mma16816(a0, qf_h, &kh[0][0]);
                    mma16816(a1, qf_h, &kh[0][2]);
                    mma16816(a2, qf_h, &kh[1][0]);
                    mma16816(a3, qf_h, &kh[1][2]);
                    mma16816(a0, qf_l, &kh[0][0]);
                    mma16816(a1, qf_l, &kh[0][2]);
                    mma16816(a2, qf_l, &kh[1][0]);
                    mma16816(a3, qf_l, &kh[1][2]);
                }
            }
        }

        // online softmax on fragments
        float tmax0 = mv0, tmax1 = mv1;
#pragma unroll
        for (int nt = 0; nt < 8; nt++) {
            acc[nt][0] *= SCALE; acc[nt][1] *= SCALE;
            acc[nt][2] *= SCALE; acc[nt][3] *= SCALE;
            tmax0 = fmaxf(tmax0, fmaxf(acc[nt][0], acc[nt][1]));
            tmax1 = fmaxf(tmax1, fmaxf(acc[nt][2], acc[nt][3]));
        }
        tmax0 = fmaxf(tmax0, __shfl_xor_sync(0xffffffffu, tmax0, 1));
        tmax0 = fmaxf(tmax0, __shfl_xor_sync(0xffffffffu, tmax0, 2));
        tmax1 = fmaxf(tmax1, __shfl_xor_sync(0xffffffffu, tmax1, 1));
        tmax1 = fmaxf(tmax1, __shfl_xor_sync(0xffffffffu, tmax1, 2));

        float alpha0 = __expf(mv0 - tmax0);
        float alpha1 = __expf(mv1 - tmax1);
        mv0 = tmax0; mv1 = tmax1;

        // P split into fp16 hi/lo in registers
        uint32_t pa_h[4][4], pa_l[4][4];
        float la0 = 0.f, la1 = 0.f;
#pragma unroll
        for (int nt = 0; nt < 8; nt++) {
            float p0 = __expf(acc[nt][0] - mv0);
            float p1 = __expf(acc[nt][1] - mv0);
            float p2 = __expf(acc[nt][2] - mv1);
            float p3 = __expf(acc[nt][3] - mv1);
            la0 += p0 + p1; la1 += p2 + p3;
            __half2 h01 = __floats2half2_rn(p0, p1);
            __half2 h23 = __floats2half2_rn(p2, p3);
            float2 f01 = __half22float2(h01), f23 = __half22float2(h23);
            int t = nt >> 1, base = (nt & 1) * 2;
            pa_h[t][base + 0] = *(uint32_t*)&h01;
            pa_h[t][base + 1] = *(uint32_t*)&h23;
            pa_l[t][base + 0] = packh(p0 - f01.x, p1 - f01.y);
            pa_l[t][base + 1] = packh(p2 - f23.x, p3 - f23.y);
        }
        l0 = l0 * alpha0 + la0;
        l1 = l1 * alpha1 + la1;

#pragma unroll
        for (int nt = 0; nt < 8; nt++) {
            O[nt][0] *= alpha0; O[nt][1] *= alpha0;
            O[nt][2] *= alpha1; O[nt][3] *= alpha1;
        }

        // O += P V (2-pass: Ph*V + Pl*V), V via trans ldmatrix
        {
            const uint32_t vbh = sb + AST_VH;
#pragma unroll
            for (int ks = 0; ks < 4; ks++) {
#pragma unroll
                for (int tq = 0; tq < 2; tq++) {
                    uint32_t vh[2][4];
#pragma unroll
                    for (int u = 0; u < 2; u++)
                        ldsm4t(vh[u], vbh + swz(ks * 16 + arl, (tq * 2 + u) * 2 + acs));
                    float* o0 = O[tq * 4 + 0]; float* o1 = O[tq * 4 + 1];
                    float* o2 = O[tq * 4 + 2]; float* o3 = O[tq * 4 + 3];
                    mma16816(o0, pa_h[ks], &vh[0][0]);
                    mma16816(o1, pa_h[ks], &vh[0][2]);
                    mma16816(o2, pa_h[ks], &vh[1][0]);
                    mma16816(o3, pa_h[ks], &vh[1][2]);
                    mma16816(o0, pa_l[ks], &vh[0][0]);
                    mma16816(o1, pa_l[ks], &vh[0][2]);
                    mma16816(o2, pa_l[ks], &vh[1][0]);
                    mma16816(o3, pa_l[ks], &vh[1][2]);
                }
            }
        }
    }

    l0 += __shfl_xor_sync(0xffffffffu, l0, 1);
    l0 += __shfl_xor_sync(0xffffffffu, l0, 2);
    l1 += __shfl_xor_sync(0xffffffffu, l1, 1);
    l1 += __shfl_xor_sync(0xffffffffu, l1, 2);
    float inv0 = 1.f / l0, inv1 = 1.f / l1;

    const size_t row0 = (size_t)(b * LQ + q0 + wid * 16 + er);
#pragma unroll
    for (int nt = 0; nt < 8; nt++) {
        int col = h * HDIM + nt * 8 + ec;
        float v0 = O[nt][0] * inv0, v1 = O[nt][1] * inv0;
        float v2 = O[nt][2] * inv1, v3 = O[nt][3] * inv1;
        __half2 h01 = __floats2half2_rn(v0, v1);
        __half2 h23 = __floats2half2_rn(v2, v3);
        float2 f01 = __half22float2(h01), f23 = __half22float2(h23);
        size_t offA = row0 * DIMC + col;
        size_t offB = (row0 + 8) * DIMC + col;
        *(uint32_t*)(Oh + offA) = *(uint32_t*)&h01;
        *(uint32_t*)(Ol + offA) = packh(v0 - f01.x, v1 - f01.y);
        *(uint32_t*)(Oh + offB) = *(uint32_t*)&h23;
        *(uint32_t*)(Ol + offB) = packh(v2 - f23.x, v3 - f23.y);
    }
}

// ---------------------------------------------------------------------------
extern "C" void kernel_launch(void* const* d_in, const int* in_sizes, int n_in,
                              void* d_out, int out_size)
{
    (void)in_sizes; (void)n_in; (void)out_size;
    const float* q     = (const float*)d_in[0];
    const float* kv    = (const float*)d_in[1];
    const float* pos   = (const float*)d_in[2];
    const float* Wq    = (const float*)d_in[3];
    const float* Wkv   = (const float*)d_in[4];
    const float* Wproj = (const float*)d_in[5];
    const float* bproj = (const float*)d_in[6];
    float* out = (float*)d_out;

    __half *qh, *ql, *kvh, *kvl, *wqh, *wql, *wkh, *wkl, *wph, *wpl;
    __half *PQh, *PQl, *PKh, *oh, *ol;
    cudaGetSymbolAddress((void**)&qh,  g_qh);   cudaGetSymbolAddress((void**)&ql,  g_ql);
    cudaGetSymbolAddress((void**)&kvh, g_kvh);  cudaGetSymbolAddress((void**)&kvl, g_kvl);
    cudaGetSymbolAddress((void**)&wqh, g_wqh);  cudaGetSymbolAddress((void**)&wql, g_wql);
    cudaGetSymbolAddress((void**)&wkh, g_wkh);  cudaGetSymbolAddress((void**)&wkl, g_wkl);
    cudaGetSymbolAddress((void**)&wph, g_wph);  cudaGetSymbolAddress((void**)&wpl, g_wpl);
    cudaGetSymbolAddress((void**)&PQh, g_PQh);  cudaGetSymbolAddress((void**)&PQl, g_PQl);
    cudaGetSymbolAddress((void**)&PKh, g_PKh);
    cudaGetSymbolAddress((void**)&oh,  g_oh);   cudaGetSymbolAddress((void**)&ol,  g_ol);

    static bool attr_done = false;
    if (!attr_done) {
        cudaFuncSetAttribute(gemm_qkv,  cudaFuncAttributeMaxDynamicSharedMemorySize, GEMM_SMEM);
        cudaFuncSetAttribute(gemm_proj, cudaFuncAttributeMaxDynamicSharedMemorySize, GEMM_SMEM);
        cudaFuncSetAttribute(attn_mma,  cudaFuncAttributeMaxDynamicSharedMemorySize, ATTN_SMEM);
        attr_done = true;
    }

    // one merged split kernel for all fp32 inputs
    {
        int grid = (int)((N4_TOT + 255) / 256);
        cvt_all<<<grid, 256>>>(
            (const float4*)q,   (uint2*)qh,  (uint2*)ql,
            (const float4*)kv,  (uint2*)kvh, (uint2*)kvl,
            (const float4*)Wq,  (uint2*)wqh, (uint2*)wql,
            (const float4*)Wkv, (uint2*)wkh, (uint2*)wkl,
            (const float4*)Wproj, (uint2*)wph, (uint2*)wpl);
    }

    // combined Q + KV projections (Q -> hi+lo, KV -> hi only)
    gemm_qkv<<<2304, 256, GEMM_SMEM>>>(qh, ql, wqh, PQh, PQl,
                                       kvh, kvl, wkh, PKh);

    // tensor-core flash attention -> split fp16 O
    attn_mma<<<dim3(LQ / 128, NHEADS, BATCH), 256, ATTN_SMEM>>>(
        PQh, PQl, PKh, pos, oh, ol);

    // output projection (fp32 + bias)
    gemm_proj<<<768, 256, GEMM_SMEM>>>(oh, ol, wph, bproj, out);
}

// round 14
// speedup vs baseline: 1.4619x; 1.0330x over previous
#include <cuda_runtime.h>
#include <cuda_fp16.h>
#include <cstdint>
#include <cstddef>

// Problem constants
#define DIMC   768
#define NHEADS 12
#define HDIM   64
#define BATCH  8
#define LQ     1024
#define LKV    1024
#define SCALE  0.125f
#define KVSTR  (2 * DIMC)       // 1536 (elements)

#define MROWS  (BATCH * LQ)     // 8192

// fp16 split scratch (hi/lo for activations; weights use hi only)
__device__ __half g_qh  [(size_t)MROWS * DIMC];
__device__ __half g_ql  [(size_t)MROWS * DIMC];
__device__ __half g_kvh [(size_t)MROWS * DIMC];
__device__ __half g_kvl [(size_t)MROWS * DIMC];
__device__ __half g_wqh [(size_t)DIMC * DIMC];
__device__ __half g_wql [(size_t)DIMC * DIMC];
__device__ __half g_wkh [(size_t)2 * DIMC * DIMC];
__device__ __half g_wkl [(size_t)2 * DIMC * DIMC];
__device__ __half g_wph [(size_t)DIMC * DIMC];
__device__ __half g_wpl [(size_t)DIMC * DIMC];
__device__ __half g_PQh [(size_t)MROWS * DIMC];
__device__ __half g_PQl [(size_t)MROWS * DIMC];
__device__ __half g_PKh [(size_t)MROWS * 2 * DIMC];   // K|V hi only
__device__ __half g_oh  [(size_t)MROWS * DIMC];
__device__ __half g_ol  [(size_t)MROWS * DIMC];

// ---------------------------------------------------------------------------
__device__ __forceinline__ uint32_t smem_u32(const void* p) {
    uint32_t a;
    asm("{ .reg .u64 t; cvta.to.shared.u64 t, %1; cvt.u32.u64 %0, t; }" : "=r"(a) : "l"(p));
    return a;
}
__device__ __forceinline__ void ldsm4(uint32_t* r, uint32_t addr) {
    asm volatile("ldmatrix.sync.aligned.m8n8.x4.shared.b16 {%0,%1,%2,%3}, [%4];"
        : "=r"(r[0]), "=r"(r[1]), "=r"(r[2]), "=r"(r[3]) : "r"(addr));
}
__device__ __forceinline__ void ldsm4t(uint32_t* r, uint32_t addr) {
    asm volatile("ldmatrix.sync.aligned.m8n8.x4.trans.shared.b16 {%0,%1,%2,%3}, [%4];"
        : "=r"(r[0]), "=r"(r[1]), "=r"(r[2]), "=r"(r[3]) : "r"(addr));
}
// fp16 mma with fp32 accumulate
__device__ __forceinline__ void mma16816(float* d, const uint32_t* a, const uint32_t* b) {
    asm volatile("mma.sync.aligned.m16n8k16.row.col.f32.f16.f16.f32 "
        "{%0,%1,%2,%3}, {%4,%5,%6,%7}, {%8,%9}, {%0,%1,%2,%3};"
        : "+f"(d[0]), "+f"(d[1]), "+f"(d[2]), "+f"(d[3])
        : "r"(a[0]), "r"(a[1]), "r"(a[2]), "r"(a[3]), "r"(b[0]), "r"(b[1]));
}
__device__ __forceinline__ void cp16(uint32_t dst, const void* src) {
    asm volatile("cp.async.cg.shared.global [%0], [%1], 16;" :: "r"(dst), "l"(src) : "memory");
}
#define CP_COMMIT() asm volatile("cp.async.commit_group;" ::: "memory")

__device__ __forceinline__ uint32_t packh(float a, float b) {
    __half2 t = __floats2half2_rn(a, b);
    return *(uint32_t*)&t;
}

// swizzled byte offset inside a 128B-row tile
__device__ __forceinline__ uint32_t swz(int row, int c16) {
    return (uint32_t)(row * 128 + ((c16 ^ (row & 7)) << 4));
}

// ---------------------------------------------------------------------------
// GEMM: tile 128(M)x128(N), 256 threads, warp 32x64 (4x2 grid), K-chunks 64,
// 2-stage cp.async, 2 CTAs/SM. fp16 2-pass: C = Ah*W + Al*W.
// ---------------------------------------------------------------------------
#define GSTG   49152          // AH 16K | AL 16K | WH 16K
#define GB_AH  0
#define GB_AL  16384
#define GB_W   32768
#define GEMM_SMEM (2 * GSTG)  // 98304

// stage 128 rows x 64 halves (16KB): 4 cp16/thread
__device__ __forceinline__ void stage128(uint32_t sdst, const __half* rowbase,
                                         int K, int k0, int tid) {
#pragma unroll
    for (int rep = 0; rep < 4; rep++) {
        int i = tid + rep * 256;
        int row = i >> 3, c16 = i & 7;
        cp16(sdst + swz(row, c16), rowbase + (size_t)row * K + k0 + c16 * 8);
    }
}

__device__ __forceinline__
void gemm_body(const __half* __restrict__ Ah, const __half* __restrict__ Al,
               const __half* __restrict__ W,
               const float* __restrict__ bias, float* __restrict__ C,
               __half* __restrict__ Ch, __half* __restrict__ Cl,
               int N, int K, int m0, int n0, char* sm)
{
    const uint32_t smb = smem_u32(sm);
    const int tid = threadIdx.x;
    const int wid = tid >> 5, lane = tid & 31;
    const int wm = wid >> 1, wn = wid & 1;   // 4x2 warp grid, warp = 32(M)x64(N)

    const __half* Ahb = Ah + (size_t)m0 * K;
    const __half* Alb = Al + (size_t)m0 * K;
    const __half* Wb  = W  + (size_t)n0 * K;

    const int g = lane >> 3, r = lane & 7;
    const int arl = (g & 1) * 8 + r;
    const int acs = g >> 1;
    const int brl = (g >> 1) * 8 + r;
    const int bcs = g & 1;

    float acc[2][8][4];
#pragma unroll
    for (int i = 0; i < 2; i++)
#pragma unroll
        for (int j = 0; j < 8; j++)
#pragma unroll
            for (int k = 0; k < 4; k++) acc[i][j][k] = 0.f;

    const int NC = K >> 6;   // 12

    {
        uint32_t sb = smb;
        stage128(sb + GB_AH, Ahb, K, 0, tid);
        stage128(sb + GB_AL, Alb, K, 0, tid);
        stage128(sb + GB_W,  Wb,  K, 0, tid);
        CP_COMMIT();
    }

    for (int c = 0; c < NC; ++c) {
        if (c + 1 < NC) {
            uint32_t sb = smb + ((c + 1) & 1) * GSTG;
            int k0 = (c + 1) << 6;
            stage128(sb + GB_AH, Ahb, K, k0, tid);
            stage128(sb + GB_AL, Alb, K, k0, tid);
            stage128(sb + GB_W,  Wb,  K, k0, tid);
            CP_COMMIT();
            asm volatile("cp.async.wait_group 1;" ::: "memory");
        } else {
            asm volatile("cp.async.wait_group 0;" ::: "memory");
        }
        __syncthreads();

        const uint32_t sb = smb + (c & 1) * GSTG;
        const uint32_t bAh = sb + GB_AH, bAl = sb + GB_AL, bW = sb + GB_W;

#pragma unroll
        for (int s = 0; s < 4; ++s) {
            uint32_t ah[2][4], al[2][4];
#pragma unroll
            for (int mt = 0; mt < 2; ++mt) {
                ldsm4(ah[mt], bAh + swz(wm * 32 + mt * 16 + arl, s * 2 + acs));
                ldsm4(al[mt], bAl + swz(wm * 32 + mt * 16 + arl, s * 2 + acs));
            }
            // W blocks consumed 2 at a time (warp owns n rows wn*64 .. wn*64+63)
#pragma unroll
            for (int pp = 0; pp < 2; ++pp) {
                uint32_t bw[2][4];
#pragma unroll
                for (int u = 0; u < 2; ++u)
                    ldsm4(bw[u], bW + swz(wn * 64 + (pp * 2 + u) * 16 + brl, s * 2 + bcs));
#pragma unroll
                for (int mt = 0; mt < 2; ++mt) {
                    float* a0 = acc[mt][pp * 4 + 0];
                    float* a1 = acc[mt][pp * 4 + 1];
                    float* a2 = acc[mt][pp * 4 + 2];
                    float* a3 = acc[mt][pp * 4 + 3];
                    mma16816(a0, ah[mt], &bw[0][0]);
                    mma16816(a1, ah[mt], &bw[0][2]);
                    mma16816(a2, ah[mt], &bw[1][0]);
                    mma16816(a3, ah[mt], &bw[1][2]);
                    mma16816(a0, al[mt], &bw[0][0]);
                    mma16816(a1, al[mt], &bw[0][2]);
                    mma16816(a2, al[mt], &bw[1][0]);
                    mma16816(a3, al[mt], &bw[1][2]);
                }
            }
        }
        __syncthreads();
    }

    const int er = lane >> 2, ec = (lane & 3) * 2;
    if (Ch) {
#pragma unroll
        for (int mt = 0; mt < 2; ++mt) {
#pragma unroll
            for (int nt = 0; nt < 8; ++nt) {
                int grow = m0 + wm * 32 + mt * 16 + er;
                int gcol = n0 + wn * 64 + nt * 8 + ec;
#pragma unroll
                for (int rr = 0; rr < 2; ++rr) {
                    float v0 = acc[mt][nt][rr * 2 + 0];
                    float v1 = acc[mt][nt][rr * 2 + 1];
                    __half2 hp = __floats2half2_rn(v0, v1);
                    size_t off = (size_t)(grow + rr * 8) * N + gcol;
                    *(uint32_t*)(Ch + off) = *(uint32_t*)&hp;
                    if (Cl) {
                        float2 hf = __half22float2(hp);
                        *(uint32_t*)(Cl + off) = packh(v0 - hf.x, v1 - hf.y);
                    }
                }
            }
        }
    } else {
#pragma unroll
        for (int mt = 0; mt < 2; ++mt) {
#pragma unroll
            for (int nt = 0; nt < 8; ++nt) {
                int grow = m0 + wm * 32 + mt * 16 + er;
                int gcol = n0 + wn * 64 + nt * 8 + ec;
                float b0 = 0.f, b1 = 0.f;
                if (bias) { b0 = bias[gcol]; b1 = bias[gcol + 1]; }
                float2 v0 = make_float2(acc[mt][nt][0] + b0, acc[mt][nt][1] + b1);
                float2 v1 = make_float2(acc[mt][nt][2] + b0, acc[mt][nt][3] + b1);
                *(float2*)(C + (size_t)grow * N + gcol) = v0;
                *(float2*)(C + (size_t)(grow + 8) * N + gcol) = v1;
            }
        }
    }
}

// Combined Q + KV projection gemm. 128x128 tiles.
// Q: 64m x 6n = 384 tiles; KV: 64m x 12n = 768 tiles. Total 1152.
__global__ __launch_bounds__(256, 2)
void gemm_qkv(const __half* __restrict__ qh, const __half* __restrict__ ql,
              const __half* __restrict__ wqh,
              __half* __restrict__ PQh, __half* __restrict__ PQl,
              const __half* __restrict__ kvh, const __half* __restrict__ kvl,
              const __half* __restrict__ wkh,
              __half* __restrict__ PKh)
{
    extern __shared__ char sm[];
    int bx = blockIdx.x;
    if (bx < 384) {
        int nb = bx % 6, mb = bx / 6;
        gemm_body(qh, ql, wqh, nullptr, nullptr, PQh, PQl,
                  DIMC, DIMC, mb * 128, nb * 128, sm);
    } else {
        int t = bx - 384;
        int nb = t % 12, mb = t / 12;
        gemm_body(kvh, kvl, wkh, nullptr, nullptr, PKh, nullptr,
                  2 * DIMC, DIMC, mb * 128, nb * 128, sm);
    }
}

// Output projection gemm (fp32 out + bias). 64m x 6n = 384 tiles.
__global__ __launch_bounds__(256, 2)
void gemm_proj(const __half* __restrict__ oh, const __half* __restrict__ ol,
               const __half* __restrict__ wph,
               const float* __restrict__ bias, float* __restrict__ out)
{
    extern __shared__ char sm[];
    int nb = blockIdx.x % 6, mb = blockIdx.x / 6;
    gemm_body(oh, ol, wph, bias, out, nullptr, nullptr,
              DIMC, DIMC, mb * 128, nb * 128, sm);
}

// ---------------------------------------------------------------------------
// One merged fp32 -> (hi,lo) fp16 split over all 5 input arrays.
// ---------------------------------------------------------------------------
#define N4_Q   ((size_t)MROWS * DIMC / 4)
#define N4_W1  ((size_t)DIMC * DIMC / 4)
#define N4_W2  ((size_t)2 * DIMC * DIMC / 4)
#define N4_TOT (N4_Q + N4_Q + N4_W1 + N4_W2 + N4_W1)

__global__ __launch_bounds__(256)
void cvt_all(const float4* __restrict__ q,   uint2* __restrict__ qh,  uint2* __restrict__ ql,
             const float4* __restrict__ kv,  uint2* __restrict__ kvh, uint2* __restrict__ kvl,
             const float4* __restrict__ wq,  uint2* __restrict__ wqh, uint2* __restrict__ wql,
             const float4* __restrict__ wkv, uint2* __restrict__ wkh, uint2* __restrict__ wkl,
             const float4* __restrict__ wp,  uint2* __restrict__ wph, uint2* __restrict__ wpl)
{
    size_t i = (size_t)blockIdx.x * blockDim.x + threadIdx.x;
    if (i >= N4_TOT) return;
    const float4* src; uint2 *hi, *lo; size_t j = i;
    if (j < N4_Q)                 { src = q;   hi = qh;  lo = ql;  }
    else if ((j -= N4_Q) < N4_Q)  { src = kv;  hi = kvh; lo = kvl; }
    else if ((j -= N4_Q) < N4_W1) { src = wq;  hi = wqh; lo = wql; }
    else if ((j -= N4_W1) < N4_W2){ src = wkv; hi = wkh; lo = wkl; }
    else { j -= N4_W2;              src = wp;  hi = wph; lo = wpl; }

    float4 x = src[j];
    __half2 h01 = __floats2half2_rn(x.x, x.y);
    __half2 h23 = __floats2half2_rn(x.z, x.w);
    float2 f01 = __half22float2(h01), f23 = __half22float2(h23);
    __half2 l01 = __floats2half2_rn(x.x - f01.x, x.y - f01.y);
    __half2 l23 = __floats2half2_rn(x.z - f23.x, x.w - f23.y);
    hi[j] = make_uint2(*(uint32_t*)&h01, *(uint32_t*)&h23);
    lo[j] = make_uint2(*(uint32_t*)&l01, *(uint32_t*)&l23);
}

// ---------------------------------------------------------------------------
// Tensor-core flash attention, fp16 2-pass (unchanged from R13).
// ---------------------------------------------------------------------------
#define AQ_H     0
#define AQ_L     16384
#define AST_BASE 32768
#define AST_KH   0
#define AST_VH   8192
#define AST_SIZE 16384
#define ATTN_SMEM (AST_BASE + 2 * AST_SIZE)   // 65536

__global__ __launch_bounds__(256, 2)
void attn_mma(const __half* __restrict__ Qh, const __half* __restrict__ Ql,
              const __half* __restrict__ KVh,
              const float* __restrict__ pos,
              __half* __restrict__ Oh, __half* __restrict__ Ol)
{
    extern __shared__ char sm[];
    const uint32_t smb = smem_u32(sm);
    const int tid = threadIdx.x, wid = tid >> 5, lane = tid & 31;
    const int b = blockIdx.z, h = blockIdx.y;
    const int q0 = blockIdx.x * 128;

    const int g = lane >> 3, r = lane & 7;
    const int arl = (g & 1) * 8 + r, acs = g >> 1;
    const int brl = (g >> 1) * 8 + r, bcs = g & 1;
    const int er = lane >> 2, ec = (lane & 3) * 2;

    // stage Q tile (hi/lo) once
    const size_t qrow0 = (size_t)(b * LQ + q0);
    for (int i = tid; i < 128 * 8; i += 256) {
        int row = i >> 3, c16 = i & 7;
        size_t off = (qrow0 + row) * DIMC + h * HDIM + c16 * 8;
        uint32_t d = swz(row, c16);
        cp16(smb + AQ_H + d, Qh + off);
        cp16(smb + AQ_L + d, Ql + off);
    }
    CP_COMMIT();

    const float* pb0 = pos + ((size_t)(h * LQ + q0 + wid * 16 + er)) * LKV + ec;
    const float* pb1 = pb0 + (size_t)8 * LKV;

    auto stage = [&](int c) {
        const uint32_t sb = smb + AST_BASE + (uint32_t)(c & 1) * AST_SIZE;
        const int kv0 = c * 64;
        const size_t kvrow0 = (size_t)(b * LKV + kv0);
#pragma unroll
        for (int jj = 0; jj < 2; jj++) {
            int i = tid + jj * 256;
            int row = i >> 3, c16 = i & 7;
            size_t off = (kvrow0 + row) * KVSTR + h * HDIM + c16 * 8;
            uint32_t d = swz(row, c16);
            cp16(sb + AST_KH + d, KVh + off);
            cp16(sb + AST_VH + d, KVh + off + DIMC);
        }
        CP_COMMIT();
    };

    float O[8][4];
#pragma unroll
    for (int nt = 0; nt < 8; nt++)
#pragma unroll
        for (int j = 0; j < 4; j++) O[nt][j] = 0.f;
    float mv0 = -1e30f, mv1 = -1e30f, l0 = 0.f, l1 = 0.f;

    stage(0);

    const int NT = LKV / 64;   // 16
    for (int c = 0; c < NT; ++c) {
        __syncthreads();
        if (c + 1 < NT) {
            stage(c + 1);
            asm volatile("cp.async.wait_group 1;" ::: "memory");
        } else {
            asm volatile("cp.async.wait_group 0;" ::: "memory");
        }
        __syncthreads();

        const uint32_t sb = smb + AST_BASE + (uint32_t)(c & 1) * AST_SIZE;

        // init S accumulator with 8*pos via direct LDG
        float acc[8][4];
        {
            const int off = c * 64;
#pragma unroll
            for (int nt = 0; nt < 8; nt++) {
                float2 p0 = *(const float2*)(pb0 + off + nt * 8);
                float2 p1 = *(const float2*)(pb1 + off + nt * 8);
                acc[nt][0] = 8.f * p0.x; acc[nt][1] = 8.f * p0.y;
                acc[nt][2] = 8.f * p1.x; acc[nt][3] = 8.f * p1.y;
            }
        }

        // S = Q K^T (2-pass: Qh*K + Ql*K)
        {
            const uint32_t qbh = smb + AQ_H, qbl = smb + AQ_L;
            const uint32_t kbh = sb + AST_KH;
#pragma unroll
            for (int ks = 0; ks < 4; ks++) {
                uint32_t qf_h[4], qf_l[4];
                ldsm4(qf_h, qbh + swz(wid * 16 + arl, ks * 2 + acs));
                ldsm4(qf_l, qbl + swz(wid * 16 + arl, ks * 2 + acs));
#pragma unroll
                for (int pp = 0; pp < 2; pp++) {
                    uint32_t kh[2][4];
#pragma unroll
                    for (int u = 0; u < 2; u++)
                        ldsm4(kh[u], kbh + swz((pp * 2 + u) * 16 + brl, ks * 2 + bcs));
                    float* a0 = acc[pp * 4 + 0]; float* a1 = acc[pp * 4 + 1];
                    float* a2 = acc[pp * 4 + 2]; float* a3 = acc[pp * 4 + 3];
                    mma16816(a0, qf_h, &kh[0][0]);
                    mma16816(a1, qf_h, &kh[0][2]);
                    mma16816(a2, qf_h, &kh[1][0]);
                    mma16816(a3, qf_h, &kh[1][2]);
                    mma16816(a0, qf_l, &kh[0][0]);
                    mma16816(a1, qf_l, &kh[0][2]);
                    mma16816(a2, qf_l, &kh[1][0]);
                    mma16816(a3, qf_l, &kh[1][2]);
                }
            }
        }

        // online softmax on fragments
        float tmax0 = mv0, tmax1 = mv1;
#pragma unroll
        for (int nt = 0; nt < 8; nt++) {
            acc[nt][0] *= SCALE; acc[nt][1] *= SCALE;
            acc[nt][2] *= SCALE; acc[nt][3] *= SCALE;
            tmax0 = fmaxf(tmax0, fmaxf(acc[nt][0], acc[nt][1]));
            tmax1 = fmaxf(tmax1, fmaxf(acc[nt][2], acc[nt][3]));
        }
        tmax0 = fmaxf(tmax0, __shfl_xor_sync(0xffffffffu, tmax0, 1));
        tmax0 = fmaxf(tmax0, __shfl_xor_sync(0xffffffffu, tmax0, 2));
        tmax1 = fmaxf(tmax1, __shfl_xor_sync(0xffffffffu, tmax1, 1));
        tmax1 = fmaxf(tmax1, __shfl_xor_sync(0xffffffffu, tmax1, 2));

        float alpha0 = __expf(mv0 - tmax0);
        float alpha1 = __expf(mv1 - tmax1);
        mv0 = tmax0; mv1 = tmax1;

        uint32_t pa_h[4][4], pa_l[4][4];
        float la0 = 0.f, la1 = 0.f;
#pragma unroll
        for (int nt = 0; nt < 8; nt++) {
            float p0 = __expf(acc[nt][0] - mv0);
            float p1 = __expf(acc[nt][1] - mv0);
            float p2 = __expf(acc[nt][2] - mv1);
            float p3 = __expf(acc[nt][3] - mv1);
            la0 += p0 + p1; la1 += p2 + p3;
            __half2 h01 = __floats2half2_rn(p0, p1);
            __half2 h23 = __floats2half2_rn(p2, p3);
            float2 f01 = __half22float2(h01), f23 = __half22float2(h23);
            int t = nt >> 1, base = (nt & 1) * 2;
            pa_h[t][base + 0] = *(uint32_t*)&h01;
            pa_h[t][base + 1] = *(uint32_t*)&h23;
            pa_l[t][base + 0] = packh(p0 - f01.x, p1 - f01.y);
            pa_l[t][base + 1] = packh(p2 - f23.x, p3 - f23.y);
        }
        l0 = l0 * alpha0 + la0;
        l1 = l1 * alpha1 + la1;

#pragma unroll
        for (int nt = 0; nt < 8; nt++) {
            O[nt][0] *= alpha0; O[nt][1] *= alpha0;
            O[nt][2] *= alpha1; O[nt][3] *= alpha1;
        }

        // O += P V (2-pass: Ph*V + Pl*V), V via trans ldmatrix
        {
            const uint32_t vbh = sb + AST_VH;
#pragma unroll
            for (int ks = 0; ks < 4; ks++) {
#pragma unroll
                for (int tq = 0; tq < 2; tq++) {
                    uint32_t vh[2][4];
#pragma unroll
                    for (int u = 0; u < 2; u++)
                        ldsm4t(vh[u], vbh + swz(ks * 16 + arl, (tq * 2 + u) * 2 + acs));
                    float* o0 = O[tq * 4 + 0]; float* o1 = O[tq * 4 + 1];
                    float* o2 = O[tq * 4 + 2]; float* o3 = O[tq * 4 + 3];
                    mma16816(o0, pa_h[ks], &vh[0][0]);
                    mma16816(o1, pa_h[ks], &vh[0][2]);
                    mma16816(o2, pa_h[ks], &vh[1][0]);
                    mma16816(o3, pa_h[ks], &vh[1][2]);
                    mma16816(o0, pa_l[ks], &vh[0][0]);
                    mma16816(o1, pa_l[ks], &vh[0][2]);
                    mma16816(o2, pa_l[ks], &vh[1][0]);
                    mma16816(o3, pa_l[ks], &vh[1][2]);
                }
            }
        }
    }

    l0 += __shfl_xor_sync(0xffffffffu, l0, 1);
    l0 += __shfl_xor_sync(0xffffffffu, l0, 2);
    l1 += __shfl_xor_sync(0xffffffffu, l1, 1);
    l1 += __shfl_xor_sync(0xffffffffu, l1, 2);
    float inv0 = 1.f / l0, inv1 = 1.f / l1;

    const size_t row0 = (size_t)(b * LQ + q0 + wid * 16 + er);
#pragma unroll
    for (int nt = 0; nt < 8; nt++) {
        int col = h * HDIM + nt * 8 + ec;
        float v0 = O[nt][0] * inv0, v1 = O[nt][1] * inv0;
        float v2 = O[nt][2] * inv1, v3 = O[nt][3] * inv1;
        __half2 h01 = __floats2half2_rn(v0, v1);
        __half2 h23 = __floats2half2_rn(v2, v3);
        float2 f01 = __half22float2(h01), f23 = __half22float2(h23);
        size_t offA = row0 * DIMC + col;
        size_t offB = (row0 + 8) * DIMC + col;
        *(uint32_t*)(Oh + offA) = *(uint32_t*)&h01;
        *(uint32_t*)(Ol + offA) = packh(v0 - f01.x, v1 - f01.y);
        *(uint32_t*)(Oh + offB) = *(uint32_t*)&h23;
        *(uint32_t*)(Ol + offB) = packh(v2 - f23.x, v3 - f23.y);
    }
}

// ---------------------------------------------------------------------------
extern "C" void kernel_launch(void* const* d_in, const int* in_sizes, int n_in,
                              void* d_out, int out_size)
{
    (void)in_sizes; (void)n_in; (void)out_size;
    const float* q     = (const float*)d_in[0];
    const float* kv    = (const float*)d_in[1];
    const float* pos   = (const float*)d_in[2];
    const float* Wq    = (const float*)d_in[3];
    const float* Wkv   = (const float*)d_in[4];
    const float* Wproj = (const float*)d_in[5];
    const float* bproj = (const float*)d_in[6];
    float* out = (float*)d_out;

    __half *qh, *ql, *kvh, *kvl, *wqh, *wql, *wkh, *wkl, *wph, *wpl;
    __half *PQh, *PQl, *PKh, *oh, *ol;
    cudaGetSymbolAddress((void**)&qh,  g_qh);   cudaGetSymbolAddress((void**)&ql,  g_ql);
    cudaGetSymbolAddress((void**)&kvh, g_kvh);  cudaGetSymbolAddress((void**)&kvl, g_kvl);
    cudaGetSymbolAddress((void**)&wqh, g_wqh);  cudaGetSymbolAddress((void**)&wql, g_wql);
    cudaGetSymbolAddress((void**)&wkh, g_wkh);  cudaGetSymbolAddress((void**)&wkl, g_wkl);
    cudaGetSymbolAddress((void**)&wph, g_wph);  cudaGetSymbolAddress((void**)&wpl, g_wpl);
    cudaGetSymbolAddress((void**)&PQh, g_PQh);  cudaGetSymbolAddress((void**)&PQl, g_PQl);
    cudaGetSymbolAddress((void**)&PKh, g_PKh);
    cudaGetSymbolAddress((void**)&oh,  g_oh);   cudaGetSymbolAddress((void**)&ol,  g_ol);

    static bool attr_done = false;
    if (!attr_done) {
        cudaFuncSetAttribute(gemm_qkv,  cudaFuncAttributeMaxDynamicSharedMemorySize, GEMM_SMEM);
        cudaFuncSetAttribute(gemm_proj, cudaFuncAttributeMaxDynamicSharedMemorySize, GEMM_SMEM);
        cudaFuncSetAttribute(attn_mma,  cudaFuncAttributeMaxDynamicSharedMemorySize, ATTN_SMEM);
        attr_done = true;
    }

    // one merged split kernel for all fp32 inputs
    {
        int grid = (int)((N4_TOT + 255) / 256);
        cvt_all<<<grid, 256>>>(
            (const float4*)q,   (uint2*)qh,  (uint2*)ql,
            (const float4*)kv,  (uint2*)kvh, (uint2*)kvl,
            (const float4*)Wq,  (uint2*)wqh, (uint2*)wql,
            (const float4*)Wkv, (uint2*)wkh, (uint2*)wkl,
            (const float4*)Wproj, (uint2*)wph, (uint2*)wpl);
    }

    // combined Q + KV projections (Q -> hi+lo, KV -> hi only)
    gemm_qkv<<<1152, 256, GEMM_SMEM>>>(qh, ql, wqh, PQh, PQl,
                                       kvh, kvl, wkh, PKh);

    // tensor-core flash attention -> split fp16 O
    attn_mma<<<dim3(LQ / 128, NHEADS, BATCH), 256, ATTN_SMEM>>>(
        PQh, PQl, PKh, pos, oh, ol);

    // output projection (fp32 + bias)
    gemm_proj<<<384, 256, GEMM_SMEM>>>(oh, ol, wph, bproj, out);
}

// round 16
// speedup vs baseline: 1.4770x; 1.0103x over previous
#include <cuda_runtime.h>
#include <cuda_fp16.h>
#include <cstdint>
#include <cstddef>

// Problem constants
#define DIMC   768
#define NHEADS 12
#define HDIM   64
#define BATCH  8
#define LQ     1024
#define LKV    1024
#define SCALE  0.125f
#define KVSTR  (2 * DIMC)       // 1536 (elements)

#define MROWS  (BATCH * LQ)     // 8192

// fp16 split scratch (hi/lo for activations; weights hi only)
__device__ __half g_qh  [(size_t)MROWS * DIMC];
__device__ __half g_ql  [(size_t)MROWS * DIMC];
__device__ __half g_kvh [(size_t)MROWS * DIMC];
__device__ __half g_kvl [(size_t)MROWS * DIMC];
__device__ __half g_wqh [(size_t)DIMC * DIMC];
__device__ __half g_wkh [(size_t)2 * DIMC * DIMC];
__device__ __half g_wph [(size_t)DIMC * DIMC];
__device__ __half g_PQh [(size_t)MROWS * DIMC];
__device__ __half g_PQl [(size_t)MROWS * DIMC];
__device__ __half g_PKh [(size_t)MROWS * 2 * DIMC];   // K|V hi only
__device__ __half g_oh  [(size_t)MROWS * DIMC];
__device__ __half g_ol  [(size_t)MROWS * DIMC];

// ---------------------------------------------------------------------------
__device__ __forceinline__ uint32_t smem_u32(const void* p) {
    uint32_t a;
    asm("{ .reg .u64 t; cvta.to.shared.u64 t, %1; cvt.u32.u64 %0, t; }" : "=r"(a) : "l"(p));
    return a;
}
__device__ __forceinline__ void ldsm4(uint32_t* r, uint32_t addr) {
    asm volatile("ldmatrix.sync.aligned.m8n8.x4.shared.b16 {%0,%1,%2,%3}, [%4];"
        : "=r"(r[0]), "=r"(r[1]), "=r"(r[2]), "=r"(r[3]) : "r"(addr));
}
__device__ __forceinline__ void ldsm4t(uint32_t* r, uint32_t addr) {
    asm volatile("ldmatrix.sync.aligned.m8n8.x4.trans.shared.b16 {%0,%1,%2,%3}, [%4];"
        : "=r"(r[0]), "=r"(r[1]), "=r"(r[2]), "=r"(r[3]) : "r"(addr));
}
__device__ __forceinline__ void mma16816(float* d, const uint32_t* a, const uint32_t* b) {
    asm volatile("mma.sync.aligned.m16n8k16.row.col.f32.f16.f16.f32 "
        "{%0,%1,%2,%3}, {%4,%5,%6,%7}, {%8,%9}, {%0,%1,%2,%3};"
        : "+f"(d[0]), "+f"(d[1]), "+f"(d[2]), "+f"(d[3])
        : "r"(a[0]), "r"(a[1]), "r"(a[2]), "r"(a[3]), "r"(b[0]), "r"(b[1]));
}
__device__ __forceinline__ void cp16(uint32_t dst, const void* src) {
    asm volatile("cp.async.cg.shared.global [%0], [%1], 16;" :: "r"(dst), "l"(src) : "memory");
}
#define CP_COMMIT() asm volatile("cp.async.commit_group;" ::: "memory")

__device__ __forceinline__ uint32_t packh(float a, float b) {
    __half2 t = __floats2half2_rn(a, b);
    return *(uint32_t*)&t;
}

// swizzled byte offset inside a 128B-row tile
__device__ __forceinline__ uint32_t swz(int row, int c16) {
    return (uint32_t)(row * 128 + ((c16 ^ (row & 7)) << 4));
}

// ---------------------------------------------------------------------------
// GEMM: tile 128(M)x128(N), 256 threads, warp 32x64 (4x2 grid), K-chunks 64,
// 2-stage cp.async, 2 CTAs/SM. fp16 2-pass: C = Ah*W + Al*W.  (R14 proven)
// ---------------------------------------------------------------------------
#define GSTG   49152          // AH 16K | AL 16K | WH 16K
#define GB_AH  0
#define GB_AL  16384
#define GB_W   32768
#define GEMM_SMEM (2 * GSTG)  // 98304

__device__ __forceinline__ void stage128(uint32_t sdst, const __half* rowbase,
                                         int K, int k0, int tid) {
#pragma unroll
    for (int rep = 0; rep < 4; rep++) {
        int i = tid + rep * 256;
        int row = i >> 3, c16 = i & 7;
        cp16(sdst + swz(row, c16), rowbase + (size_t)row * K + k0 + c16 * 8);
    }
}

__device__ __forceinline__
void gemm_body(const __half* __restrict__ Ah, const __half* __restrict__ Al,
               const __half* __restrict__ W,
               const float* __restrict__ bias, float* __restrict__ C,
               __half* __restrict__ Ch, __half* __restrict__ Cl,
               int N, int K, int m0, int n0, char* sm)
{
    const uint32_t smb = smem_u32(sm);
    const int tid = threadIdx.x;
    const int wid = tid >> 5, lane = tid & 31;
    const int wm = wid >> 1, wn = wid & 1;   // warp = 32(M) x 64(N)

    const __half* Ahb = Ah + (size_t)m0 * K;
    const __half* Alb = Al + (size_t)m0 * K;
    const __half* Wb  = W  + (size_t)n0 * K;

    const int g = lane >> 3, r = lane & 7;
    const int arl = (g & 1) * 8 + r;
    const int acs = g >> 1;
    const int brl = (g >> 1) * 8 + r;
    const int bcs = g & 1;

    float acc[2][8][4];
#pragma unroll
    for (int i = 0; i < 2; i++)
#pragma unroll
        for (int j = 0; j < 8; j++)
#pragma unroll
            for (int k = 0; k < 4; k++) acc[i][j][k] = 0.f;

    const int NC = K >> 6;   // 12

    {
        uint32_t sb = smb;
        stage128(sb + GB_AH, Ahb, K, 0, tid);
        stage128(sb + GB_AL, Alb, K, 0, tid);
        stage128(sb + GB_W,  Wb,  K, 0, tid);
        CP_COMMIT();
    }

    for (int c = 0; c < NC; ++c) {
        if (c + 1 < NC) {
            uint32_t sb = smb + ((c + 1) & 1) * GSTG;
            int k0 = (c + 1) << 6;
            stage128(sb + GB_AH, Ahb, K, k0, tid);
            stage128(sb + GB_AL, Alb, K, k0, tid);
            stage128(sb + GB_W,  Wb,  K, k0, tid);
            CP_COMMIT();
            asm volatile("cp.async.wait_group 1;" ::: "memory");
        } else {
            asm volatile("cp.async.wait_group 0;" ::: "memory");
        }
        __syncthreads();

        const uint32_t sb = smb + (c & 1) * GSTG;
        const uint32_t bAh = sb + GB_AH, bAl = sb + GB_AL, bW = sb + GB_W;

#pragma unroll
        for (int s = 0; s < 4; ++s) {
            uint32_t ah[2][4], al[2][4];
#pragma unroll
            for (int mt = 0; mt < 2; ++mt) {
                ldsm4(ah[mt], bAh + swz(wm * 32 + mt * 16 + arl, s * 2 + acs));
                ldsm4(al[mt], bAl + swz(wm * 32 + mt * 16 + arl, s * 2 + acs));
            }
#pragma unroll
            for (int pp = 0; pp < 2; ++pp) {
                uint32_t bw[2][4];
#pragma unroll
                for (int u = 0; u < 2; ++u)
                    ldsm4(bw[u], bW + swz(wn * 64 + (pp * 2 + u) * 16 + brl, s * 2 + bcs));
#pragma unroll
                for (int mt = 0; mt < 2; ++mt) {
                    float* a0 = acc[mt][pp * 4 + 0];
                    float* a1 = acc[mt][pp * 4 + 1];
                    float* a2 = acc[mt][pp * 4 + 2];
                    float* a3 = acc[mt][pp * 4 + 3];
                    mma16816(a0, ah[mt], &bw[0][0]);
                    mma16816(a1, ah[mt], &bw[0][2]);
                    mma16816(a2, ah[mt], &bw[1][0]);
                    mma16816(a3, ah[mt], &bw[1][2]);
                    mma16816(a0, al[mt], &bw[0][0]);
                    mma16816(a1, al[mt], &bw[0][2]);
                    mma16816(a2, al[mt], &bw[1][0]);
                    mma16816(a3, al[mt], &bw[1][2]);
                }
            }
        }
        __syncthreads();
    }

    const int er = lane >> 2, ec = (lane & 3) * 2;
    if (Ch) {
#pragma unroll
        for (int mt = 0; mt < 2; ++mt) {
#pragma unroll
            for (int nt = 0; nt < 8; ++nt) {
                int grow = m0 + wm * 32 + mt * 16 + er;
                int gcol = n0 + wn * 64 + nt * 8 + ec;
#pragma unroll
                for (int rr = 0; rr < 2; ++rr) {
                    float v0 = acc[mt][nt][rr * 2 + 0];
                    float v1 = acc[mt][nt][rr * 2 + 1];
                    __half2 hp = __floats2half2_rn(v0, v1);
                    size_t off = (size_t)(grow + rr * 8) * N + gcol;
                    *(uint32_t*)(Ch + off) = *(uint32_t*)&hp;
                    if (Cl) {
                        float2 hf = __half22float2(hp);
                        *(uint32_t*)(Cl + off) = packh(v0 - hf.x, v1 - hf.y);
                    }
                }
            }
        }
    } else {
#pragma unroll
        for (int mt = 0; mt < 2; ++mt) {
#pragma unroll
            for (int nt = 0; nt < 8; ++nt) {
                int grow = m0 + wm * 32 + mt * 16 + er;
                int gcol = n0 + wn * 64 + nt * 8 + ec;
                float b0 = 0.f, b1 = 0.f;
                if (bias) { b0 = bias[gcol]; b1 = bias[gcol + 1]; }
                float2 v0 = make_float2(acc[mt][nt][0] + b0, acc[mt][nt][1] + b1);
                float2 v1 = make_float2(acc[mt][nt][2] + b0, acc[mt][nt][3] + b1);
                *(float2*)(C + (size_t)grow * N + gcol) = v0;
                *(float2*)(C + (size_t)(grow + 8) * N + gcol) = v1;
            }
        }
    }
}

// Combined Q + KV projection gemm. 128x128 tiles.
__global__ __launch_bounds__(256, 2)
void gemm_qkv(const __half* __restrict__ qh, const __half* __restrict__ ql,
              const __half* __restrict__ wqh,
              __half* __restrict__ PQh, __half* __restrict__ PQl,
              const __half* __restrict__ kvh, const __half* __restrict__ kvl,
              const __half* __restrict__ wkh,
              __half* __restrict__ PKh)
{
    extern __shared__ char sm[];
    int bx = blockIdx.x;
    if (bx < 384) {
        int nb = bx % 6, mb = bx / 6;
        gemm_body(qh, ql, wqh, nullptr, nullptr, PQh, PQl,
                  DIMC, DIMC, mb * 128, nb * 128, sm);
    } else {
        int t = bx - 384;
        int nb = t % 12, mb = t / 12;
        gemm_body(kvh, kvl, wkh, nullptr, nullptr, PKh, nullptr,
                  2 * DIMC, DIMC, mb * 128, nb * 128, sm);
    }
}

// Output projection gemm (fp32 out + bias).
__global__ __launch_bounds__(256, 2)
void gemm_proj(const __half* __restrict__ oh, const __half* __restrict__ ol,
               const __half* __restrict__ wph,
               const float* __restrict__ bias, float* __restrict__ out)
{
    extern __shared__ char sm[];
    int nb = blockIdx.x % 6, mb = blockIdx.x / 6;
    gemm_body(oh, ol, wph, bias, out, nullptr, nullptr,
              DIMC, DIMC, mb * 128, nb * 128, sm);
}

// ---------------------------------------------------------------------------
// cvt: fp32 -> fp16 split, 4 float4 units per thread (MLP=4), block-uniform
// segment decode (all boundaries are multiples of 1024 units).
// Blocks: [0,1536) q hi+lo | [1536,3072) kv hi+lo | [3072,3216) Wq hi
//         [3216,3504) Wkv hi | [3504,3648) Wproj hi
// ---------------------------------------------------------------------------
#define CVT_GRID 3648

__global__ __launch_bounds__(256)
void cvt_all(const float4* __restrict__ q,   uint2* __restrict__ qh,  uint2* __restrict__ ql,
             const float4* __restrict__ kv,  uint2* __restrict__ kvh, uint2* __restrict__ kvl,
             const float4* __restrict__ wq,  uint2* __restrict__ wqh,
             const float4* __restrict__ wkv, uint2* __restrict__ wkh,
             const float4* __restrict__ wp,  uint2* __restrict__ wph)
{
    const int bidx = blockIdx.x;
    const float4* src; uint2* hi; uint2* lo;
    size_t base;
    if (bidx < 1536)      { src = q;   hi = qh;  lo = ql;      base = (size_t)bidx * 1024; }
    else if (bidx < 3072) { src = kv;  hi = kvh; lo = kvl;     base = (size_t)(bidx - 1536) * 1024; }
    else if (bidx < 3216) { src = wq;  hi = wqh; lo = nullptr; base = (size_t)(bidx - 3072) * 1024; }
    else if (bidx < 3504) { src = wkv; hi = wkh; lo = nullptr; base = (size_t)(bidx - 3216) * 1024; }
    else                  { src = wp;  hi = wph; lo = nullptr; base = (size_t)(bidx - 3504) * 1024; }

    const size_t i0 = base + threadIdx.x;
    float4 x[4];
#pragma unroll
    for (int j = 0; j < 4; j++) x[j] = src[i0 + (size_t)j * 256];
#pragma unroll
    for (int j = 0; j < 4; j++) {
        __half2 h01 = __floats2half2_rn(x[j].x, x[j].y);
        __half2 h23 = __floats2half2_rn(x[j].z, x[j].w);
        hi[i0 + (size_t)j * 256] = make_uint2(*(uint32_t*)&h01, *(uint32_t*)&h23);
        if (lo) {
            float2 f01 = __half22float2(h01), f23 = __half22float2(h23);
            __half2 l01 = __floats2half2_rn(x[j].x - f01.x, x[j].y - f01.y);
            __half2 l23 = __floats2half2_rn(x[j].z - f23.x, x[j].w - f23.y);
            lo[i0 + (size_t)j * 256] = make_uint2(*(uint32_t*)&l01, *(uint32_t*)&l23);
        }
    }
}

// ---------------------------------------------------------------------------
// Tensor-core flash attention, fp16 2-pass (R13/R14 proven).
// ---------------------------------------------------------------------------
#define AQ_H     0
#define AQ_L     16384
#define AST_BASE 32768
#define AST_KH   0
#define AST_VH   8192
#define AST_SIZE 16384
#define ATTN_SMEM (AST_BASE + 2 * AST_SIZE)   // 65536

__global__ __launch_bounds__(256, 2)
void attn_mma(const __half* __restrict__ Qh, const __half* __restrict__ Ql,
              const __half* __restrict__ KVh,
              const float* __restrict__ pos,
              __half* __restrict__ Oh, __half* __restrict__ Ol)
{
    extern __shared__ char sm[];
    const uint32_t smb = smem_u32(sm);
    const int tid = threadIdx.x, wid = tid >> 5, lane = tid & 31;
    const int b = blockIdx.z, h = blockIdx.y;
    const int q0 = blockIdx.x * 128;

    const int g = lane >> 3, r = lane & 7;
    const int arl = (g & 1) * 8 + r, acs = g >> 1;
    const int brl = (g >> 1) * 8 + r, bcs = g & 1;
    const int er = lane >> 2, ec = (lane & 3) * 2;

    const size_t qrow0 = (size_t)(b * LQ + q0);
    for (int i = tid; i < 128 * 8; i += 256) {
        int row = i >> 3, c16 = i & 7;
        size_t off = (qrow0 + row) * DIMC + h * HDIM + c16 * 8;
        uint32_t d = swz(row, c16);
        cp16(smb + AQ_H + d, Qh + off);
        cp16(smb + AQ_L + d, Ql + off);
    }
    CP_COMMIT();

    const float* pb0 = pos + ((size_t)(h * LQ + q0 + wid * 16 + er)) * LKV + ec;
    const float* pb1 = pb0 + (size_t)8 * LKV;

    auto stage = [&](int c) {
        const uint32_t sb = smb + AST_BASE + (uint32_t)(c & 1) * AST_SIZE;
        const int kv0 = c * 64;
        const size_t kvrow0 = (size_t)(b * LKV + kv0);
#pragma unroll
        for (int jj = 0; jj < 2; jj++) {
            int i = tid + jj * 256;
            int row = i >> 3, c16 = i & 7;
            size_t off = (kvrow0 + row) * KVSTR + h * HDIM + c16 * 8;
            uint32_t d = swz(row, c16);
            cp16(sb + AST_KH + d, KVh + off);
            cp16(sb + AST_VH + d, KVh + off + DIMC);
        }
        CP_COMMIT();
    };

    float O[8][4];
#pragma unroll
    for (int nt = 0; nt < 8; nt++)
#pragma unroll
        for (int j = 0; j < 4; j++) O[nt][j] = 0.f;
    float mv0 = -1e30f, mv1 = -1e30f, l0 = 0.f, l1 = 0.f;

    stage(0);

    const int NT = LKV / 64;   // 16
    for (int c = 0; c < NT; ++c) {
        __syncthreads();
        if (c + 1 < NT) {
            stage(c + 1);
            asm volatile("cp.async.wait_group 1;" ::: "memory");
        } else {
            asm volatile("cp.async.wait_group 0;" ::: "memory");
        }
        __syncthreads();

        const uint32_t sb = smb + AST_BASE + (uint32_t)(c & 1) * AST_SIZE;

        // init S accumulator with 8*pos via direct LDG
        float acc[8][4];
        {
            const int off = c * 64;
#pragma unroll
            for (int nt = 0; nt < 8; nt++) {
                float2 p0 = *(const float2*)(pb0 + off + nt * 8);
                float2 p1 = *(const float2*)(pb1 + off + nt * 8);
                acc[nt][0] = 8.f * p0.x; acc[nt][1] = 8.f * p0.y;
                acc[nt][2] = 8.f * p1.x; acc[nt][3] = 8.f * p1.y;
            }
        }

        // S = Q K^T (2-pass: Qh*K + Ql*K)
        {
            const uint32_t qbh = smb + AQ_H, qbl = smb + AQ_L;
            const uint32_t kbh = sb + AST_KH;
#pragma unroll
            for (int ks = 0; ks < 4; ks++) {
                uint32_t qf_h[4], qf_l[4];
                ldsm4(qf_h, qbh + swz(wid * 16 + arl, ks * 2 + acs));
                ldsm4(qf_l, qbl + swz(wid * 16 + arl, ks * 2 + acs));
#pragma unroll
                for (int pp = 0; pp < 2; pp++) {
                    uint32_t kh[2][4];
#pragma unroll
                    for (int u = 0; u < 2; u++)
                        ldsm4(kh[u], kbh + swz((pp * 2 + u) * 16 + brl, ks * 2 + bcs));
                    float* a0 = acc[pp * 4 + 0]; float* a1 = acc[pp * 4 + 1];
                    float* a2 = acc[pp * 4 + 2]; float* a3 = acc[pp * 4 + 3];
                    mma16816(a0, qf_h, &kh[0][0]);
                    mma16816(a1, qf_h, &kh[0][2]);
                    mma16816(a2, qf_h, &kh[1][0]);
                    mma16816(a3, qf_h, &kh[1][2]);
                    mma16816(a0, qf_l, &kh[0][0]);
                    mma16816(a1, qf_l, &kh[0][2]);
                    mma16816(a2, qf_l, &kh[1][0]);
                    mma16816(a3, qf_l, &kh[1][2]);
                }
            }
        }

        // online softmax on fragments
        float tmax0 = mv0, tmax1 = mv1;
#pragma unroll
        for (int nt = 0; nt < 8; nt++) {
            acc[nt][0] *= SCALE; acc[nt][1] *= SCALE;
            acc[nt][2] *= SCALE; acc[nt][3] *= SCALE;
            tmax0 = fmaxf(tmax0, fmaxf(acc[nt][0], acc[nt][1]));
            tmax1 = fmaxf(tmax1, fmaxf(acc[nt][2], acc[nt][3]));
        }
        tmax0 = fmaxf(tmax0, __shfl_xor_sync(0xffffffffu, tmax0, 1));
        tmax0 = fmaxf(tmax0, __shfl_xor_sync(0xffffffffu, tmax0, 2));
        tmax1 = fmaxf(tmax1, __shfl_xor_sync(0xffffffffu, tmax1, 1));
        tmax1 = fmaxf(tmax1, __shfl_xor_sync(0xffffffffu, tmax1, 2));

        float alpha0 = __expf(mv0 - tmax0);
        float alpha1 = __expf(mv1 - tmax1);
        mv0 = tmax0; mv1 = tmax1;

        uint32_t pa_h[4][4], pa_l[4][4];
        float la0 = 0.f, la1 = 0.f;
#pragma unroll
        for (int nt = 0; nt < 8; nt++) {
            float p0 = __expf(acc[nt][0] - mv0);
            float p1 = __expf(acc[nt][1] - mv0);
            float p2 = __expf(acc[nt][2] - mv1);
            float p3 = __expf(acc[nt][3] - mv1);
            la0 += p0 + p1; la1 += p2 + p3;
            __half2 h01 = __floats2half2_rn(p0, p1);
            __half2 h23 = __floats2half2_rn(p2, p3);
            float2 f01 = __half22float2(h01), f23 = __half22float2(h23);
            int t = nt >> 1, base = (nt & 1) * 2;
            pa_h[t][base + 0] = *(uint32_t*)&h01;
            pa_h[t][base + 1] = *(uint32_t*)&h23;
            pa_l[t][base + 0] = packh(p0 - f01.x, p1 - f01.y);
            pa_l[t][base + 1] = packh(p2 - f23.x, p3 - f23.y);
        }
        l0 = l0 * alpha0 + la0;
        l1 = l1 * alpha1 + la1;

#pragma unroll
        for (int nt = 0; nt < 8; nt++) {
            O[nt][0] *= alpha0; O[nt][1] *= alpha0;
            O[nt][2] *= alpha1; O[nt][3] *= alpha1;
        }

        // O += P V (2-pass: Ph*V + Pl*V), V via trans ldmatrix
        {
            const uint32_t vbh = sb + AST_VH;
#pragma unroll
            for (int ks = 0; ks < 4; ks++) {
#pragma unroll
                for (int tq = 0; tq < 2; tq++) {
                    uint32_t vh[2][4];
#pragma unroll
                    for (int u = 0; u < 2; u++)
                        ldsm4t(vh[u], vbh + swz(ks * 16 + arl, (tq * 2 + u) * 2 + acs));
                    float* o0 = O[tq * 4 + 0]; float* o1 = O[tq * 4 + 1];
                    float* o2 = O[tq * 4 + 2]; float* o3 = O[tq * 4 + 3];
                    mma16816(o0, pa_h[ks], &vh[0][0]);
                    mma16816(o1, pa_h[ks], &vh[0][2]);
                    mma16816(o2, pa_h[ks], &vh[1][0]);
                    mma16816(o3, pa_h[ks], &vh[1][2]);
                    mma16816(o0, pa_l[ks], &vh[0][0]);
                    mma16816(o1, pa_l[ks], &vh[0][2]);
                    mma16816(o2, pa_l[ks], &vh[1][0]);
                    mma16816(o3, pa_l[ks], &vh[1][2]);
                }
            }
        }
    }

    l0 += __shfl_xor_sync(0xffffffffu, l0, 1);
    l0 += __shfl_xor_sync(0xffffffffu, l0, 2);
    l1 += __shfl_xor_sync(0xffffffffu, l1, 1);
    l1 += __shfl_xor_sync(0xffffffffu, l1, 2);
    float inv0 = 1.f / l0, inv1 = 1.f / l1;

    const size_t row0 = (size_t)(b * LQ + q0 + wid * 16 + er);
#pragma unroll
    for (int nt = 0; nt < 8; nt++) {
        int col = h * HDIM + nt * 8 + ec;
        float v0 = O[nt][0] * inv0, v1 = O[nt][1] * inv0;
        float v2 = O[nt][2] * inv1, v3 = O[nt][3] * inv1;
        __half2 h01 = __floats2half2_rn(v0, v1);
        __half2 h23 = __floats2half2_rn(v2, v3);
        float2 f01 = __half22float2(h01), f23 = __half22float2(h23);
        size_t offA = row0 * DIMC + col;
        size_t offB = (row0 + 8) * DIMC + col;
        *(uint32_t*)(Oh + offA) = *(uint32_t*)&h01;
        *(uint32_t*)(Ol + offA) = packh(v0 - f01.x, v1 - f01.y);
        *(uint32_t*)(Oh + offB) = *(uint32_t*)&h23;
        *(uint32_t*)(Ol + offB) = packh(v2 - f23.x, v3 - f23.y);
    }
}

// ---------------------------------------------------------------------------
extern "C" void kernel_launch(void* const* d_in, const int* in_sizes, int n_in,
                              void* d_out, int out_size)
{
    (void)in_sizes; (void)n_in; (void)out_size;
    const float* q     = (const float*)d_in[0];
    const float* kv    = (const float*)d_in[1];
    const float* pos   = (const float*)d_in[2];
    const float* Wq    = (const float*)d_in[3];
    const float* Wkv   = (const float*)d_in[4];
    const float* Wproj = (const float*)d_in[5];
    const float* bproj = (const float*)d_in[6];
    float* out = (float*)d_out;

    __half *qh, *ql, *kvh, *kvl, *wqh, *wkh, *wph;
    __half *PQh, *PQl, *PKh, *oh, *ol;
    cudaGetSymbolAddress((void**)&qh,  g_qh);   cudaGetSymbolAddress((void**)&ql,  g_ql);
    cudaGetSymbolAddress((void**)&kvh, g_kvh);  cudaGetSymbolAddress((void**)&kvl, g_kvl);
    cudaGetSymbolAddress((void**)&wqh, g_wqh);
    cudaGetSymbolAddress((void**)&wkh, g_wkh);
    cudaGetSymbolAddress((void**)&wph, g_wph);
    cudaGetSymbolAddress((void**)&PQh, g_PQh);  cudaGetSymbolAddress((void**)&PQl, g_PQl);
    cudaGetSymbolAddress((void**)&PKh, g_PKh);
    cudaGetSymbolAddress((void**)&oh,  g_oh);   cudaGetSymbolAddress((void**)&ol,  g_ol);

    static bool attr_done = false;
    if (!attr_done) {
        cudaFuncSetAttribute(gemm_qkv,  cudaFuncAttributeMaxDynamicSharedMemorySize, GEMM_SMEM);
        cudaFuncSetAttribute(gemm_proj, cudaFuncAttributeMaxDynamicSharedMemorySize, GEMM_SMEM);
        cudaFuncSetAttribute(attn_mma,  cudaFuncAttributeMaxDynamicSharedMemorySize, ATTN_SMEM);
        attr_done = true;
    }

    // fp32 -> fp16 split (activations hi+lo; weights hi only)
    cvt_all<<<CVT_GRID, 256>>>(
        (const float4*)q,   (uint2*)qh,  (uint2*)ql,
        (const float4*)kv,  (uint2*)kvh, (uint2*)kvl,
        (const float4*)Wq,  (uint2*)wqh,
        (const float4*)Wkv, (uint2*)wkh,
        (const float4*)Wproj, (uint2*)wph);

    // combined Q + KV projections (Q -> hi+lo, KV -> hi only)
    gemm_qkv<<<1152, 256, GEMM_SMEM>>>(qh, ql, wqh, PQh, PQl,
                                       kvh, kvl, wkh, PKh);

    // tensor-core flash attention -> split fp16 O
    attn_mma<<<dim3(LQ / 128, NHEADS, BATCH), 256, ATTN_SMEM>>>(
        PQh, PQl, PKh, pos, oh, ol);

    // output projection (fp32 + bias)
    gemm_proj<<<384, 256, GEMM_SMEM>>>(oh, ol, wph, bproj, out);
}